// round 2
// baseline (speedup 1.0000x reference)
#include <cuda_runtime.h>
#include <cuda_bf16.h>
#include <math_constants.h>

// Problem constants
#define BB 4
#define TT 2048
#define DD 1024
#define HH 16
#define DKK 64
#define FFN 4096
#define MM (BB * TT)   // 8192 rows

// ---------------- scratch (device globals; no runtime allocation) ------------
__device__ float g_q[MM * DD];
__device__ float g_k[MM * DD];
__device__ float g_v[MM * DD];
__device__ float g_attn[MM * DD];
__device__ float g_proj[MM * DD];
__device__ float g_x1[MM * DD];
__device__ float g_ffn1[(size_t)MM * FFN];
__device__ float g_ffn2[MM * DD];

// ---------------- SGEMM: C[M,N] = A[M,K] @ W[N,K]^T + bias, opt ReLU ---------
// Classic 128x128x8 register-blocked fp32 GEMM, 256 threads, 8x8 per thread.
// All dims are multiples of the tile sizes for this problem -> no bounds checks.
template <bool RELU>
__global__ __launch_bounds__(256) void sgemm_nt_kernel(
    const float* __restrict__ A, const float* __restrict__ W,
    const float* __restrict__ bias, float* __restrict__ C,
    int M, int N, int K)
{
    constexpr int BM = 128, BN = 128, BK = 8, TM = 8, TN = 8;
    __shared__ float As[BK][BM];
    __shared__ float Bs[BK][BN];

    const int tid = threadIdx.x;
    const int bx = blockIdx.x, by = blockIdx.y;
    const int row0 = by * BM;
    const int col0 = bx * BN;
    const int tx = tid & 15;   // 0..15 -> N
    const int ty = tid >> 4;   // 0..15 -> M

    const int loadRow = tid >> 1;        // 0..127
    const int loadC4  = (tid & 1) * 4;   // 0 or 4

    const float* Aptr = A + (size_t)(row0 + loadRow) * K + loadC4;
    const float* Wptr = W + (size_t)(col0 + loadRow) * K + loadC4;

    float acc[TM][TN];
    #pragma unroll
    for (int i = 0; i < TM; i++)
        #pragma unroll
        for (int j = 0; j < TN; j++) acc[i][j] = 0.0f;

    for (int k0 = 0; k0 < K; k0 += BK) {
        float4 av = *(const float4*)(Aptr + k0);
        float4 wv = *(const float4*)(Wptr + k0);
        As[loadC4 + 0][loadRow] = av.x;
        As[loadC4 + 1][loadRow] = av.y;
        As[loadC4 + 2][loadRow] = av.z;
        As[loadC4 + 3][loadRow] = av.w;
        Bs[loadC4 + 0][loadRow] = wv.x;
        Bs[loadC4 + 1][loadRow] = wv.y;
        Bs[loadC4 + 2][loadRow] = wv.z;
        Bs[loadC4 + 3][loadRow] = wv.w;
        __syncthreads();

        #pragma unroll
        for (int k = 0; k < BK; k++) {
            float rm[TM], rn[TN];
            float4 m0 = *(const float4*)&As[k][ty * TM];
            float4 m1 = *(const float4*)&As[k][ty * TM + 4];
            float4 n0 = *(const float4*)&Bs[k][tx * TN];
            float4 n1 = *(const float4*)&Bs[k][tx * TN + 4];
            rm[0] = m0.x; rm[1] = m0.y; rm[2] = m0.z; rm[3] = m0.w;
            rm[4] = m1.x; rm[5] = m1.y; rm[6] = m1.z; rm[7] = m1.w;
            rn[0] = n0.x; rn[1] = n0.y; rn[2] = n0.z; rn[3] = n0.w;
            rn[4] = n1.x; rn[5] = n1.y; rn[6] = n1.z; rn[7] = n1.w;
            #pragma unroll
            for (int i = 0; i < TM; i++)
                #pragma unroll
                for (int j = 0; j < TN; j++)
                    acc[i][j] = fmaf(rm[i], rn[j], acc[i][j]);
        }
        __syncthreads();
    }

    // epilogue: + bias, optional relu, vectorized stores
    float bsv[TN];
    #pragma unroll
    for (int j = 0; j < TN; j++) bsv[j] = bias[col0 + tx * TN + j];

    #pragma unroll
    for (int i = 0; i < TM; i++) {
        const int r = row0 + ty * TM + i;
        float* crow = C + (size_t)r * N + col0 + tx * TN;
        float out[TN];
        #pragma unroll
        for (int j = 0; j < TN; j++) {
            float v = acc[i][j] + bsv[j];
            out[j] = RELU ? fmaxf(v, 0.0f) : v;
        }
        *(float4*)(crow + 0) = make_float4(out[0], out[1], out[2], out[3]);
        *(float4*)(crow + 4) = make_float4(out[4], out[5], out[6], out[7]);
    }
}

// ---------------- Flash attention (causal), fp32 ------------------------------
// One block per (q-tile of 64 rows, head, batch). 64 threads; each thread owns
// one query row: q[64] and acc[64] live in registers. K/V tiles of 32 keys in
// shared memory (broadcast reads -> conflict-free).
__global__ __launch_bounds__(64) void attn_kernel(
    const float* __restrict__ Q, const float* __restrict__ Kg,
    const float* __restrict__ Vg, float* __restrict__ O)
{
    constexpr int KT = 32;
    __shared__ float Ks[KT][DKK];
    __shared__ float Vs[KT][DKK];

    const int tid = threadIdx.x;
    const int qt = blockIdx.x;   // 0..31
    const int h  = blockIdx.y;
    const int b  = blockIdx.z;
    const int qi = qt * 64 + tid;

    const float* qp = Q + ((size_t)(b * TT + qi)) * DD + h * DKK;
    float q[DKK];
    #pragma unroll
    for (int i = 0; i < 16; i++) {
        float4 v = *(const float4*)(qp + i * 4);
        q[i * 4 + 0] = v.x; q[i * 4 + 1] = v.y;
        q[i * 4 + 2] = v.z; q[i * 4 + 3] = v.w;
    }

    float acc[DKK];
    #pragma unroll
    for (int d = 0; d < DKK; d++) acc[d] = 0.0f;
    float m = -1e30f, l = 0.0f;

    const int kt_max = 2 * qt + 1;   // last 32-key tile overlapping causal range
    for (int kt = 0; kt <= kt_max; kt++) {
        const int krow0 = kt * KT;
        // cooperative load of K/V tile: 512 float4s, 8 per thread, coalesced
        #pragma unroll
        for (int r = 0; r < 8; r++) {
            int e = r * 64 + tid;
            int row = e >> 4;
            int c4  = (e & 15) * 4;
            size_t gofs = ((size_t)(b * TT + krow0 + row)) * DD + h * DKK + c4;
            *(float4*)&Ks[row][c4] = *(const float4*)(Kg + gofs);
            *(float4*)&Vs[row][c4] = *(const float4*)(Vg + gofs);
        }
        __syncthreads();

        float s[KT];
        #pragma unroll
        for (int j = 0; j < KT; j++) {
            float sum = 0.0f;
            #pragma unroll
            for (int k4 = 0; k4 < 16; k4++) {
                float4 kv = *(const float4*)&Ks[j][k4 * 4];
                sum = fmaf(q[k4 * 4 + 0], kv.x, sum);
                sum = fmaf(q[k4 * 4 + 1], kv.y, sum);
                sum = fmaf(q[k4 * 4 + 2], kv.z, sum);
                sum = fmaf(q[k4 * 4 + 3], kv.w, sum);
            }
            s[j] = (krow0 + j <= qi) ? sum * 0.125f : -1e30f;
        }

        float mt = m;
        #pragma unroll
        for (int j = 0; j < KT; j++) mt = fmaxf(mt, s[j]);

        float corr = __expf(m - mt);
        l *= corr;
        #pragma unroll
        for (int d = 0; d < DKK; d++) acc[d] *= corr;

        #pragma unroll
        for (int j = 0; j < KT; j++) {
            float p = __expf(s[j] - mt);
            l += p;
            #pragma unroll
            for (int d4 = 0; d4 < 16; d4++) {
                float4 vv = *(const float4*)&Vs[j][d4 * 4];
                acc[d4 * 4 + 0] = fmaf(p, vv.x, acc[d4 * 4 + 0]);
                acc[d4 * 4 + 1] = fmaf(p, vv.y, acc[d4 * 4 + 1]);
                acc[d4 * 4 + 2] = fmaf(p, vv.z, acc[d4 * 4 + 2]);
                acc[d4 * 4 + 3] = fmaf(p, vv.w, acc[d4 * 4 + 3]);
            }
        }
        m = mt;
        __syncthreads();
    }

    const float inv = 1.0f / l;
    float* op = O + ((size_t)(b * TT + qi)) * DD + h * DKK;
    #pragma unroll
    for (int i = 0; i < 16; i++) {
        float4 v = make_float4(acc[i * 4 + 0] * inv, acc[i * 4 + 1] * inv,
                               acc[i * 4 + 2] * inv, acc[i * 4 + 3] * inv);
        *(float4*)(op + i * 4) = v;
    }
}

// ---------------- fused residual-add + LayerNorm ------------------------------
// One block per row (1024 elems), 256 threads x 4 elems.
__global__ __launch_bounds__(256) void add_ln_kernel(
    const float* __restrict__ A, const float* __restrict__ Bv,
    const float* __restrict__ g, const float* __restrict__ be,
    float* __restrict__ out)
{
    const int row = blockIdx.x;
    const int tid = threadIdx.x;
    const size_t base = (size_t)row * DD + tid * 4;

    float4 av = *(const float4*)(A + base);
    float4 bv = *(const float4*)(Bv + base);
    float y0 = av.x + bv.x, y1 = av.y + bv.y, y2 = av.z + bv.z, y3 = av.w + bv.w;

    float s  = y0 + y1 + y2 + y3;
    float ss = y0 * y0 + y1 * y1 + y2 * y2 + y3 * y3;

    #pragma unroll
    for (int o = 16; o > 0; o >>= 1) {
        s  += __shfl_xor_sync(0xffffffffu, s, o);
        ss += __shfl_xor_sync(0xffffffffu, ss, o);
    }
    __shared__ float red_s[8], red_ss[8];
    const int wid = tid >> 5;
    if ((tid & 31) == 0) { red_s[wid] = s; red_ss[wid] = ss; }
    __syncthreads();
    float ts = 0.0f, tss = 0.0f;
    #pragma unroll
    for (int w = 0; w < 8; w++) { ts += red_s[w]; tss += red_ss[w]; }

    const float mu   = ts * (1.0f / DD);
    const float var  = tss * (1.0f / DD) - mu * mu;
    const float rstd = rsqrtf(var + 1e-5f);

    float4 gv  = *(const float4*)(g  + tid * 4);
    float4 bev = *(const float4*)(be + tid * 4);
    float4 ov;
    ov.x = (y0 - mu) * rstd * gv.x + bev.x;
    ov.y = (y1 - mu) * rstd * gv.y + bev.y;
    ov.z = (y2 - mu) * rstd * gv.z + bev.z;
    ov.w = (y3 - mu) * rstd * gv.w + bev.w;
    *(float4*)(out + base) = ov;
}

// ---------------- launch ------------------------------------------------------
extern "C" void kernel_launch(void* const* d_in, const int* in_sizes, int n_in,
                              void* d_out, int out_size)
{
    const float* x   = (const float*)d_in[0];
    const float* WQ  = (const float*)d_in[1];
    const float* bQ  = (const float*)d_in[2];
    const float* WK  = (const float*)d_in[3];
    const float* bK  = (const float*)d_in[4];
    const float* WV  = (const float*)d_in[5];
    const float* bV  = (const float*)d_in[6];
    const float* WO  = (const float*)d_in[7];
    const float* bO  = (const float*)d_in[8];
    const float* W1  = (const float*)d_in[9];
    const float* b1  = (const float*)d_in[10];
    const float* W2  = (const float*)d_in[11];
    const float* b2  = (const float*)d_in[12];
    const float* g1  = (const float*)d_in[13];
    const float* be1 = (const float*)d_in[14];
    const float* g2  = (const float*)d_in[15];
    const float* be2 = (const float*)d_in[16];
    float* out = (float*)d_out;

    // resolve device-global scratch addresses (pure lookup, capture-safe)
    float *p_q, *p_k, *p_v, *p_attn, *p_proj, *p_x1, *p_ffn1, *p_ffn2;
    cudaGetSymbolAddress((void**)&p_q,    g_q);
    cudaGetSymbolAddress((void**)&p_k,    g_k);
    cudaGetSymbolAddress((void**)&p_v,    g_v);
    cudaGetSymbolAddress((void**)&p_attn, g_attn);
    cudaGetSymbolAddress((void**)&p_proj, g_proj);
    cudaGetSymbolAddress((void**)&p_x1,   g_x1);
    cudaGetSymbolAddress((void**)&p_ffn1, g_ffn1);
    cudaGetSymbolAddress((void**)&p_ffn2, g_ffn2);

    const dim3 gD(DD / 128, MM / 128);     // (8, 64)
    const dim3 gF(FFN / 128, MM / 128);    // (32, 64)

    // Q/K/V projections
    sgemm_nt_kernel<false><<<gD, 256>>>(x, WQ, bQ, p_q, MM, DD, DD);
    sgemm_nt_kernel<false><<<gD, 256>>>(x, WK, bK, p_k, MM, DD, DD);
    sgemm_nt_kernel<false><<<gD, 256>>>(x, WV, bV, p_v, MM, DD, DD);

    // causal attention
    attn_kernel<<<dim3(TT / 64, HH, BB), 64>>>(p_q, p_k, p_v, p_attn);

    // output projection + LN1
    sgemm_nt_kernel<false><<<gD, 256>>>(p_attn, WO, bO, p_proj, MM, DD, DD);
    add_ln_kernel<<<MM, 256>>>(x, p_proj, g1, be1, p_x1);

    // FFN + LN2
    sgemm_nt_kernel<true ><<<gF, 256>>>(p_x1, W1, b1, p_ffn1, MM, FFN, DD);
    sgemm_nt_kernel<false><<<gD, 256>>>(p_ffn1, W2, b2, p_ffn2, MM, DD, FFN);
    add_ln_kernel<<<MM, 256>>>(p_x1, p_ffn2, g2, be2, out);
}

// round 4
// speedup vs baseline: 1.9965x; 1.9965x over previous
#include <cuda_runtime.h>
#include <cuda_bf16.h>
#include <math_constants.h>
#include <cstdint>

// Problem constants
#define BB 4
#define TT 2048
#define DD 1024
#define HH 16
#define DKK 64
#define FFN 4096
#define MM (BB * TT)   // 8192 rows

// ---------------- scratch (device globals; no runtime allocation) ------------
__device__ float g_q[MM * DD];
__device__ float g_k[MM * DD];
__device__ float g_v[MM * DD];
__device__ float g_attn[MM * DD];
__device__ float g_proj[MM * DD];
__device__ float g_x1[MM * DD];
__device__ float g_ffn1[(size_t)MM * FFN];
__device__ float g_ffn2[MM * DD];

// ---------------- helpers -----------------------------------------------------
__device__ __forceinline__ uint32_t f2tf32(float f) {
    uint32_t r;
    asm("cvt.rna.tf32.f32 %0, %1;" : "=r"(r) : "f"(f));
    return r;
}

__device__ __forceinline__ void cp_async16(uint32_t smem_addr, const void* gptr) {
    asm volatile("cp.async.ca.shared.global [%0], [%1], 16;\n"
                 :: "r"(smem_addr), "l"(gptr));
}
__device__ __forceinline__ void cp_commit() {
    asm volatile("cp.async.commit_group;\n" ::: "memory");
}
__device__ __forceinline__ void cp_wait0() {
    asm volatile("cp.async.wait_group 0;\n" ::: "memory");
}

__device__ __forceinline__ void mma_tf32(float c[4], const uint32_t a[4], const uint32_t b[2]) {
    asm volatile(
        "mma.sync.aligned.m16n8k8.row.col.f32.tf32.tf32.f32 "
        "{%0,%1,%2,%3}, {%4,%5,%6,%7}, {%8,%9}, {%0,%1,%2,%3};\n"
        : "+f"(c[0]), "+f"(c[1]), "+f"(c[2]), "+f"(c[3])
        : "r"(a[0]), "r"(a[1]), "r"(a[2]), "r"(a[3]), "r"(b[0]), "r"(b[1]));
}

// ---------------- TF32 tensor-core GEMM: C = A[M,K] @ W[N,K]^T + bias ---------
// 128x128x32 CTA tile, 256 threads = 8 warps in 2(M)x4(N), warp tile 64x32.
// cp.async double-buffered smem. mma.sync m16n8k8 tf32, fp32 accum.
constexpr int LDA = 36;  // 32 + 4 pad -> conflict-free fragment loads
constexpr int STAGE_F = 128 * LDA;            // floats per stage per matrix
constexpr int GEMM_SMEM = 2 * 2 * STAGE_F * 4; // bytes (2 stages x A,B)

template <bool RELU>
__global__ __launch_bounds__(256, 2) void gemm_tf32_nt(
    const float* __restrict__ A, const float* __restrict__ W,
    const float* __restrict__ bias, float* __restrict__ C,
    int M, int N, int K)
{
    extern __shared__ float smem[];
    float* As = smem;                 // [2][128][LDA]
    float* Bs = smem + 2 * STAGE_F;   // [2][128][LDA]

    const int tid  = threadIdx.x;
    const int lane = tid & 31;
    const int wid  = tid >> 5;
    const int warp_m = wid >> 2;      // 0..1
    const int warp_n = wid & 3;       // 0..3
    const int row0 = blockIdx.y * 128;
    const int col0 = blockIdx.x * 128;

    // loader mapping: 128 rows x 8 float4-cols, 4 rows per thread
    const int lr = tid >> 3;          // 0..31
    const int lc = (tid & 7) * 4;     // 0,4,..28

    const float* gA = A + (size_t)(row0 + lr) * K + lc;
    const float* gW = W + (size_t)(col0 + lr) * K + lc;

    uint32_t sA_base, sB_base;
    {
        sA_base = (uint32_t)__cvta_generic_to_shared(As);
        sB_base = (uint32_t)__cvta_generic_to_shared(Bs);
    }

    auto load_stage = [&](int buf, int kiter) {
        const size_t kofs = (size_t)kiter * 32;
        #pragma unroll
        for (int r = 0; r < 4; r++) {
            const int row = lr + r * 32;
            uint32_t so = (uint32_t)((buf * STAGE_F + row * LDA + lc) * 4);
            cp_async16(sA_base + so, gA + (size_t)(r * 32) * K + kofs);
            cp_async16(sB_base + so, gW + (size_t)(r * 32) * K + kofs);
        }
    };

    float c[4][4][4];
    #pragma unroll
    for (int mi = 0; mi < 4; mi++)
        #pragma unroll
        for (int ni = 0; ni < 4; ni++)
            #pragma unroll
            for (int r = 0; r < 4; r++) c[mi][ni][r] = 0.0f;

    const int iters = K / 32;
    load_stage(0, 0);
    cp_commit();

    int buf = 0;
    for (int it = 0; it < iters; it++) {
        cp_wait0();
        __syncthreads();
        if (it + 1 < iters) { load_stage(buf ^ 1, it + 1); cp_commit(); }

        const float* Ab = As + buf * STAGE_F;
        const float* Bb = Bs + buf * STAGE_F;
        const int g  = lane >> 2;     // 0..7
        const int t4 = lane & 3;      // 0..3

        #pragma unroll
        for (int ks = 0; ks < 4; ks++) {
            const int kk = ks * 8 + t4;
            uint32_t a[4][4], b[4][2];
            #pragma unroll
            for (int mi = 0; mi < 4; mi++) {
                const int ar = warp_m * 64 + mi * 16 + g;
                a[mi][0] = f2tf32(Ab[ar * LDA + kk]);
                a[mi][1] = f2tf32(Ab[(ar + 8) * LDA + kk]);
                a[mi][2] = f2tf32(Ab[ar * LDA + kk + 4]);
                a[mi][3] = f2tf32(Ab[(ar + 8) * LDA + kk + 4]);
            }
            #pragma unroll
            for (int ni = 0; ni < 4; ni++) {
                const int br = warp_n * 32 + ni * 8 + g;
                b[ni][0] = f2tf32(Bb[br * LDA + kk]);
                b[ni][1] = f2tf32(Bb[br * LDA + kk + 4]);
            }
            #pragma unroll
            for (int mi = 0; mi < 4; mi++)
                #pragma unroll
                for (int ni = 0; ni < 4; ni++)
                    mma_tf32(c[mi][ni], a[mi], b[ni]);
        }
        __syncthreads();
        buf ^= 1;
    }

    // epilogue: + bias, opt relu; C frag: c0=(r,c) c1=(r,c+1) c2=(r+8,c) c3=(r+8,c+1)
    const int g  = lane >> 2;
    const int t4 = lane & 3;
    #pragma unroll
    for (int ni = 0; ni < 4; ni++) {
        const int col = col0 + warp_n * 32 + ni * 8 + t4 * 2;
        const float b0 = bias[col], b1 = bias[col + 1];
        #pragma unroll
        for (int mi = 0; mi < 4; mi++) {
            const int row = row0 + warp_m * 64 + mi * 16 + g;
            float v0 = c[mi][ni][0] + b0;
            float v1 = c[mi][ni][1] + b1;
            float v2 = c[mi][ni][2] + b0;
            float v3 = c[mi][ni][3] + b1;
            if (RELU) {
                v0 = fmaxf(v0, 0.0f); v1 = fmaxf(v1, 0.0f);
                v2 = fmaxf(v2, 0.0f); v3 = fmaxf(v3, 0.0f);
            }
            *(float2*)(C + (size_t)row * N + col)       = make_float2(v0, v1);
            *(float2*)(C + (size_t)(row + 8) * N + col) = make_float2(v2, v3);
        }
    }
}

// ---------------- Flash attention (causal), fp32, 2 threads per q-row ---------
// Block = 128 threads = 64 query rows x 2 halves; each thread owns 32 dims.
// Partner threads (lane^1) exchange partial dot products via shfl.
__global__ __launch_bounds__(128, 3) void attn_kernel(
    const float* __restrict__ Q, const float* __restrict__ Kg,
    const float* __restrict__ Vg, float* __restrict__ O)
{
    constexpr int KT = 32;
    __shared__ float Ks[KT][DKK];
    __shared__ float Vs[KT][DKK];

    const int tid  = threadIdx.x;
    const int row  = tid >> 1;        // 0..63 q-row within tile
    const int half = tid & 1;         // which 32 dims
    const int qt = blockIdx.x;        // 0..31
    const int h  = blockIdx.y;
    const int b  = blockIdx.z;
    const int qi = qt * 64 + row;

    const float* qp = Q + ((size_t)(b * TT + qi)) * DD + h * DKK + half * 32;
    float q[32];
    #pragma unroll
    for (int i = 0; i < 8; i++) {
        float4 v = *(const float4*)(qp + i * 4);
        q[i * 4 + 0] = v.x; q[i * 4 + 1] = v.y;
        q[i * 4 + 2] = v.z; q[i * 4 + 3] = v.w;
    }

    float acc[32];
    #pragma unroll
    for (int d = 0; d < 32; d++) acc[d] = 0.0f;
    float m = -1e30f, l = 0.0f;

    const int kt_max = 2 * qt + 1;
    for (int kt = 0; kt <= kt_max; kt++) {
        const int krow0 = kt * KT;
        // cooperative K/V tile load: 512 float4s, 4 per thread, coalesced
        #pragma unroll
        for (int r = 0; r < 4; r++) {
            int e = r * 128 + tid;
            int rr = e >> 4;
            int c4 = (e & 15) * 4;
            size_t gofs = ((size_t)(b * TT + krow0 + rr)) * DD + h * DKK + c4;
            *(float4*)&Ks[rr][c4] = *(const float4*)(Kg + gofs);
            *(float4*)&Vs[rr][c4] = *(const float4*)(Vg + gofs);
        }
        __syncthreads();

        float s[KT];
        #pragma unroll
        for (int j = 0; j < KT; j++) {
            float sum = 0.0f;
            #pragma unroll
            for (int k4 = 0; k4 < 8; k4++) {
                float4 kv = *(const float4*)&Ks[j][half * 32 + k4 * 4];
                sum = fmaf(q[k4 * 4 + 0], kv.x, sum);
                sum = fmaf(q[k4 * 4 + 1], kv.y, sum);
                sum = fmaf(q[k4 * 4 + 2], kv.z, sum);
                sum = fmaf(q[k4 * 4 + 3], kv.w, sum);
            }
            sum += __shfl_xor_sync(0xffffffffu, sum, 1);   // full 64-dim dot
            s[j] = (krow0 + j <= qi) ? sum * 0.125f : -1e30f;
        }

        float mt = m;
        #pragma unroll
        for (int j = 0; j < KT; j++) mt = fmaxf(mt, s[j]);

        float corr = __expf(m - mt);
        l *= corr;
        #pragma unroll
        for (int d = 0; d < 32; d++) acc[d] *= corr;

        #pragma unroll
        for (int j = 0; j < KT; j++) {
            float p = __expf(s[j] - mt);
            l += p;
            #pragma unroll
            for (int d4 = 0; d4 < 8; d4++) {
                float4 vv = *(const float4*)&Vs[j][half * 32 + d4 * 4];
                acc[d4 * 4 + 0] = fmaf(p, vv.x, acc[d4 * 4 + 0]);
                acc[d4 * 4 + 1] = fmaf(p, vv.y, acc[d4 * 4 + 1]);
                acc[d4 * 4 + 2] = fmaf(p, vv.z, acc[d4 * 4 + 2]);
                acc[d4 * 4 + 3] = fmaf(p, vv.w, acc[d4 * 4 + 3]);
            }
        }
        m = mt;
        __syncthreads();
    }

    const float inv = 1.0f / l;
    float* op = O + ((size_t)(b * TT + qi)) * DD + h * DKK + half * 32;
    #pragma unroll
    for (int i = 0; i < 8; i++) {
        float4 v = make_float4(acc[i * 4 + 0] * inv, acc[i * 4 + 1] * inv,
                               acc[i * 4 + 2] * inv, acc[i * 4 + 3] * inv);
        *(float4*)(op + i * 4) = v;
    }
}

// ---------------- fused residual-add + LayerNorm ------------------------------
__global__ __launch_bounds__(256) void add_ln_kernel(
    const float* __restrict__ A, const float* __restrict__ Bv,
    const float* __restrict__ g, const float* __restrict__ be,
    float* __restrict__ out)
{
    const int row = blockIdx.x;
    const int tid = threadIdx.x;
    const size_t base = (size_t)row * DD + tid * 4;

    float4 av = *(const float4*)(A + base);
    float4 bv = *(const float4*)(Bv + base);
    float y0 = av.x + bv.x, y1 = av.y + bv.y, y2 = av.z + bv.z, y3 = av.w + bv.w;

    float s  = y0 + y1 + y2 + y3;
    float ss = y0 * y0 + y1 * y1 + y2 * y2 + y3 * y3;

    #pragma unroll
    for (int o = 16; o > 0; o >>= 1) {
        s  += __shfl_xor_sync(0xffffffffu, s, o);
        ss += __shfl_xor_sync(0xffffffffu, ss, o);
    }
    __shared__ float red_s[8], red_ss[8];
    const int wid = tid >> 5;
    if ((tid & 31) == 0) { red_s[wid] = s; red_ss[wid] = ss; }
    __syncthreads();
    float ts = 0.0f, tss = 0.0f;
    #pragma unroll
    for (int w = 0; w < 8; w++) { ts += red_s[w]; tss += red_ss[w]; }

    const float mu   = ts * (1.0f / DD);
    const float var  = tss * (1.0f / DD) - mu * mu;
    const float rstd = rsqrtf(var + 1e-5f);

    float4 gv  = *(const float4*)(g  + tid * 4);
    float4 bev = *(const float4*)(be + tid * 4);
    float4 ov;
    ov.x = (y0 - mu) * rstd * gv.x + bev.x;
    ov.y = (y1 - mu) * rstd * gv.y + bev.y;
    ov.z = (y2 - mu) * rstd * gv.z + bev.z;
    ov.w = (y3 - mu) * rstd * gv.w + bev.w;
    *(float4*)(out + base) = ov;
}

// ---------------- launch ------------------------------------------------------
extern "C" void kernel_launch(void* const* d_in, const int* in_sizes, int n_in,
                              void* d_out, int out_size)
{
    const float* x   = (const float*)d_in[0];
    const float* WQ  = (const float*)d_in[1];
    const float* bQ  = (const float*)d_in[2];
    const float* WK  = (const float*)d_in[3];
    const float* bK  = (const float*)d_in[4];
    const float* WV  = (const float*)d_in[5];
    const float* bV  = (const float*)d_in[6];
    const float* WO  = (const float*)d_in[7];
    const float* bO  = (const float*)d_in[8];
    const float* W1  = (const float*)d_in[9];
    const float* b1  = (const float*)d_in[10];
    const float* W2  = (const float*)d_in[11];
    const float* b2  = (const float*)d_in[12];
    const float* g1  = (const float*)d_in[13];
    const float* be1 = (const float*)d_in[14];
    const float* g2  = (const float*)d_in[15];
    const float* be2 = (const float*)d_in[16];
    float* out = (float*)d_out;

    float *p_q, *p_k, *p_v, *p_attn, *p_proj, *p_x1, *p_ffn1, *p_ffn2;
    cudaGetSymbolAddress((void**)&p_q,    g_q);
    cudaGetSymbolAddress((void**)&p_k,    g_k);
    cudaGetSymbolAddress((void**)&p_v,    g_v);
    cudaGetSymbolAddress((void**)&p_attn, g_attn);
    cudaGetSymbolAddress((void**)&p_proj, g_proj);
    cudaGetSymbolAddress((void**)&p_x1,   g_x1);
    cudaGetSymbolAddress((void**)&p_ffn1, g_ffn1);
    cudaGetSymbolAddress((void**)&p_ffn2, g_ffn2);

    // allow >48KB dynamic smem for the GEMM (idempotent, capture-safe)
    cudaFuncSetAttribute(gemm_tf32_nt<false>,
                         cudaFuncAttributeMaxDynamicSharedMemorySize, GEMM_SMEM);
    cudaFuncSetAttribute(gemm_tf32_nt<true>,
                         cudaFuncAttributeMaxDynamicSharedMemorySize, GEMM_SMEM);

    const dim3 gD(DD / 128, MM / 128);     // (8, 64)
    const dim3 gF(FFN / 128, MM / 128);    // (32, 64)

    // Q/K/V projections
    gemm_tf32_nt<false><<<gD, 256, GEMM_SMEM>>>(x, WQ, bQ, p_q, MM, DD, DD);
    gemm_tf32_nt<false><<<gD, 256, GEMM_SMEM>>>(x, WK, bK, p_k, MM, DD, DD);
    gemm_tf32_nt<false><<<gD, 256, GEMM_SMEM>>>(x, WV, bV, p_v, MM, DD, DD);

    // causal attention
    attn_kernel<<<dim3(TT / 64, HH, BB), 128>>>(p_q, p_k, p_v, p_attn);

    // output projection + LN1
    gemm_tf32_nt<false><<<gD, 256, GEMM_SMEM>>>(p_attn, WO, bO, p_proj, MM, DD, DD);
    add_ln_kernel<<<MM, 256>>>(x, p_proj, g1, be1, p_x1);

    // FFN + LN2
    gemm_tf32_nt<true ><<<gF, 256, GEMM_SMEM>>>(p_x1, W1, b1, p_ffn1, MM, FFN, DD);
    gemm_tf32_nt<false><<<gD, 256, GEMM_SMEM>>>(p_ffn1, W2, b2, p_ffn2, MM, DD, FFN);
    add_ln_kernel<<<MM, 256>>>(p_x1, p_ffn2, g2, be2, out);
}

// round 7
// speedup vs baseline: 3.7466x; 1.8765x over previous
#include <cuda_runtime.h>
#include <cuda_bf16.h>
#include <math_constants.h>
#include <cstdint>

// Problem constants
#define BB 4
#define TT 2048
#define DD 1024
#define HH 16
#define DKK 64
#define FFN 4096
#define MM (BB * TT)   // 8192 rows

// ---------------- scratch (device globals; no runtime allocation) ------------
__device__ float g_q[MM * DD];
__device__ float g_k[MM * DD];
__device__ float g_v[MM * DD];
__device__ float g_attn[MM * DD];
__device__ float g_proj[MM * DD];
__device__ float g_x1[MM * DD];
__device__ float g_ffn1[(size_t)MM * FFN];
__device__ float g_ffn2[MM * DD];

// ---------------- helpers -----------------------------------------------------
__device__ __forceinline__ uint32_t f2tf32(float f) {
    uint32_t r;
    asm("cvt.rna.tf32.f32 %0, %1;" : "=r"(r) : "f"(f));
    return r;
}
__device__ __forceinline__ float tf32r(float f) {      // round to tf32, keep fp32 layout
    return __uint_as_float(f2tf32(f));
}

__device__ __forceinline__ void cp_async16(uint32_t smem_addr, const void* gptr) {
    asm volatile("cp.async.ca.shared.global [%0], [%1], 16;\n"
                 :: "r"(smem_addr), "l"(gptr));
}
__device__ __forceinline__ void cp_commit() {
    asm volatile("cp.async.commit_group;\n" ::: "memory");
}
__device__ __forceinline__ void cp_wait0() {
    asm volatile("cp.async.wait_group 0;\n" ::: "memory");
}

__device__ __forceinline__ void mma_tf32(float c[4], const uint32_t a[4], const uint32_t b[2]) {
    asm volatile(
        "mma.sync.aligned.m16n8k8.row.col.f32.tf32.tf32.f32 "
        "{%0,%1,%2,%3}, {%4,%5,%6,%7}, {%8,%9}, {%0,%1,%2,%3};\n"
        : "+f"(c[0]), "+f"(c[1]), "+f"(c[2]), "+f"(c[3])
        : "r"(a[0]), "r"(a[1]), "r"(a[2]), "r"(a[3]), "r"(b[0]), "r"(b[1]));
}

// ---------------- TF32 tensor-core GEMM: C = A[M,K] @ W[N,K]^T + bias ---------
constexpr int LDA = 36;  // 32 + 4 pad -> conflict-free fragment loads
constexpr int STAGE_F = 128 * LDA;
constexpr int GEMM_SMEM = 2 * 2 * STAGE_F * 4;

template <bool RELU>
__global__ __launch_bounds__(256, 2) void gemm_tf32_nt(
    const float* __restrict__ A, const float* __restrict__ W,
    const float* __restrict__ bias, float* __restrict__ C,
    int M, int N, int K)
{
    extern __shared__ float smem[];
    float* As = smem;
    float* Bs = smem + 2 * STAGE_F;

    const int tid  = threadIdx.x;
    const int lane = tid & 31;
    const int wid  = tid >> 5;
    const int warp_m = wid >> 2;
    const int warp_n = wid & 3;
    const int row0 = blockIdx.y * 128;
    const int col0 = blockIdx.x * 128;

    const int lr = tid >> 3;
    const int lc = (tid & 7) * 4;

    const float* gA = A + (size_t)(row0 + lr) * K + lc;
    const float* gW = W + (size_t)(col0 + lr) * K + lc;

    uint32_t sA_base = (uint32_t)__cvta_generic_to_shared(As);
    uint32_t sB_base = (uint32_t)__cvta_generic_to_shared(Bs);

    auto load_stage = [&](int buf, int kiter) {
        const size_t kofs = (size_t)kiter * 32;
        #pragma unroll
        for (int r = 0; r < 4; r++) {
            const int row = lr + r * 32;
            uint32_t so = (uint32_t)((buf * STAGE_F + row * LDA + lc) * 4);
            cp_async16(sA_base + so, gA + (size_t)(r * 32) * K + kofs);
            cp_async16(sB_base + so, gW + (size_t)(r * 32) * K + kofs);
        }
    };

    float c[4][4][4];
    #pragma unroll
    for (int mi = 0; mi < 4; mi++)
        #pragma unroll
        for (int ni = 0; ni < 4; ni++)
            #pragma unroll
            for (int r = 0; r < 4; r++) c[mi][ni][r] = 0.0f;

    const int iters = K / 32;
    load_stage(0, 0);
    cp_commit();

    int buf = 0;
    for (int it = 0; it < iters; it++) {
        cp_wait0();
        __syncthreads();
        if (it + 1 < iters) { load_stage(buf ^ 1, it + 1); cp_commit(); }

        const float* Ab = As + buf * STAGE_F;
        const float* Bb = Bs + buf * STAGE_F;
        const int g  = lane >> 2;
        const int t4 = lane & 3;

        #pragma unroll
        for (int ks = 0; ks < 4; ks++) {
            const int kk = ks * 8 + t4;
            uint32_t a[4][4], b[4][2];
            #pragma unroll
            for (int mi = 0; mi < 4; mi++) {
                const int ar = warp_m * 64 + mi * 16 + g;
                a[mi][0] = f2tf32(Ab[ar * LDA + kk]);
                a[mi][1] = f2tf32(Ab[(ar + 8) * LDA + kk]);
                a[mi][2] = f2tf32(Ab[ar * LDA + kk + 4]);
                a[mi][3] = f2tf32(Ab[(ar + 8) * LDA + kk + 4]);
            }
            #pragma unroll
            for (int ni = 0; ni < 4; ni++) {
                const int br = warp_n * 32 + ni * 8 + g;
                b[ni][0] = f2tf32(Bb[br * LDA + kk]);
                b[ni][1] = f2tf32(Bb[br * LDA + kk + 4]);
            }
            #pragma unroll
            for (int mi = 0; mi < 4; mi++)
                #pragma unroll
                for (int ni = 0; ni < 4; ni++)
                    mma_tf32(c[mi][ni], a[mi], b[ni]);
        }
        __syncthreads();
        buf ^= 1;
    }

    const int g  = lane >> 2;
    const int t4 = lane & 3;
    #pragma unroll
    for (int ni = 0; ni < 4; ni++) {
        const int col = col0 + warp_n * 32 + ni * 8 + t4 * 2;
        const float b0 = bias[col], b1 = bias[col + 1];
        #pragma unroll
        for (int mi = 0; mi < 4; mi++) {
            const int row = row0 + warp_m * 64 + mi * 16 + g;
            float v0 = c[mi][ni][0] + b0;
            float v1 = c[mi][ni][1] + b1;
            float v2 = c[mi][ni][2] + b0;
            float v3 = c[mi][ni][3] + b1;
            if (RELU) {
                v0 = fmaxf(v0, 0.0f); v1 = fmaxf(v1, 0.0f);
                v2 = fmaxf(v2, 0.0f); v3 = fmaxf(v3, 0.0f);
            }
            *(float2*)(C + (size_t)row * N + col)       = make_float2(v0, v1);
            *(float2*)(C + (size_t)(row + 8) * N + col) = make_float2(v2, v3);
        }
    }
}

// ---------------- Tensor-core flash attention (causal, tf32 mma) --------------
// Block: 128 threads = 4 warps; 64 q-rows per block (16 per warp), dk = 64.
// K/V tiles of 64 keys, cp.async double-buffered; all mma operands pre-rounded
// to tf32 in smem. P round-trips through smem (per-warp region, syncwarp only).
constexpr int LDQ = 68;   // Q/K/P row stride (floats): g*4+t4 banks distinct
constexpr int LDV = 72;   // V row stride: t4*8+g banks distinct
constexpr int AQ_OFF = 0;                 // Qs [64][68]
constexpr int AK_OFF = 64 * LDQ;          // Ks [2][64][68]
constexpr int AV_OFF = AK_OFF + 2 * 64 * LDQ;  // Vs [2][64][72]
constexpr int AP_OFF = AV_OFF + 2 * 64 * LDV;  // Ps [64][68]
constexpr int ATTN_SMEM_F = AP_OFF + 64 * LDQ;
constexpr int ATTN_SMEM = ATTN_SMEM_F * 4;     // 106496 bytes

__device__ __forceinline__ void round_tile64(float* base, int tid, int stride) {
    // 64 rows x 64 cols -> tf32 (rna) in place; 8 float4 per thread
    #pragma unroll
    for (int i = 0; i < 8; i++) {
        int e = i * 128 + tid;
        int rr = e >> 4;
        int c4 = (e & 15) * 4;
        float4* p = (float4*)(base + rr * stride + c4);
        float4 v = *p;
        v.x = tf32r(v.x); v.y = tf32r(v.y); v.z = tf32r(v.z); v.w = tf32r(v.w);
        *p = v;
    }
}

__global__ __launch_bounds__(128, 2) void attn_mma_kernel(
    const float* __restrict__ Q, const float* __restrict__ Kg,
    const float* __restrict__ Vg, float* __restrict__ O)
{
    extern __shared__ float sm[];
    float* Qs = sm + AQ_OFF;
    float* Ps = sm + AP_OFF;

    const int tid  = threadIdx.x;
    const int lane = tid & 31;
    const int warp = tid >> 5;
    const int g    = lane >> 2;
    const int t4   = lane & 3;
    const int qt = blockIdx.x;   // 0..31
    const int h  = blockIdx.y;
    const int b  = blockIdx.z;

    const uint32_t s_base = (uint32_t)__cvta_generic_to_shared(sm);

    // ---- async load Q tile + K/V tile 0
    {
        const float* Qp = Q + ((size_t)(b * TT + qt * 64)) * DD + h * 64;
        #pragma unroll
        for (int i = 0; i < 8; i++) {
            int e = i * 128 + tid;
            int rr = e >> 4;
            int c4 = (e & 15) * 4;
            cp_async16(s_base + (uint32_t)((AQ_OFF + rr * LDQ + c4) * 4),
                       Qp + (size_t)rr * DD + c4);
        }
    }
    auto load_kv = [&](int buf, int kt) {
        const float* Kp = Kg + ((size_t)(b * TT + kt * 64)) * DD + h * 64;
        const float* Vp = Vg + ((size_t)(b * TT + kt * 64)) * DD + h * 64;
        #pragma unroll
        for (int i = 0; i < 8; i++) {
            int e = i * 128 + tid;
            int rr = e >> 4;
            int c4 = (e & 15) * 4;
            cp_async16(s_base + (uint32_t)((AK_OFF + buf * 64 * LDQ + rr * LDQ + c4) * 4),
                       Kp + (size_t)rr * DD + c4);
            cp_async16(s_base + (uint32_t)((AV_OFF + buf * 64 * LDV + rr * LDV + c4) * 4),
                       Vp + (size_t)rr * DD + c4);
        }
    };
    load_kv(0, 0);
    cp_commit();

    float m0 = -1e30f, m1 = -1e30f, l0 = 0.0f, l1 = 0.0f;
    float co[8][4];
    #pragma unroll
    for (int ni = 0; ni < 8; ni++)
        #pragma unroll
        for (int r = 0; r < 4; r++) co[ni][r] = 0.0f;

    const int row0g = qt * 64 + warp * 16 + g;   // global q index (low row)
    float* Pw0 = Ps + (warp * 16 + g) * LDQ;
    float* Pw1 = Pw0 + 8 * LDQ;
    const float* Qw = Qs + (warp * 16) * LDQ;

    for (int kt = 0; kt <= qt; kt++) {
        const int buf = kt & 1;
        float* KsB = sm + AK_OFF + buf * 64 * LDQ;
        float* VsB = sm + AV_OFF + buf * 64 * LDV;

        cp_wait0();
        __syncthreads();
        if (kt < qt) { load_kv(buf ^ 1, kt + 1); cp_commit(); }

        if (kt == 0) round_tile64(Qs, tid, LDQ);
        round_tile64(KsB, tid, LDQ);
        round_tile64(VsB, tid, LDV);
        __syncthreads();

        // ---- S = Q @ K^T (16x64 per warp)
        float cs[8][4];
        #pragma unroll
        for (int ni = 0; ni < 8; ni++)
            #pragma unroll
            for (int r = 0; r < 4; r++) cs[ni][r] = 0.0f;

        #pragma unroll
        for (int ks = 0; ks < 8; ks++) {
            const int kk = ks * 8 + t4;
            uint32_t a[4];
            a[0] = __float_as_uint(Qw[g * LDQ + kk]);
            a[1] = __float_as_uint(Qw[(g + 8) * LDQ + kk]);
            a[2] = __float_as_uint(Qw[g * LDQ + kk + 4]);
            a[3] = __float_as_uint(Qw[(g + 8) * LDQ + kk + 4]);
            #pragma unroll
            for (int ni = 0; ni < 8; ni++) {
                uint32_t bb[2];
                bb[0] = __float_as_uint(KsB[(ni * 8 + g) * LDQ + kk]);
                bb[1] = __float_as_uint(KsB[(ni * 8 + g) * LDQ + kk + 4]);
                mma_tf32(cs[ni], a, bb);
            }
        }

        // ---- scale + causal mask (only diagonal tile needs masking)
        const float SC = 0.125f;
        float rm0 = -1e30f, rm1 = -1e30f;
        #pragma unroll
        for (int ni = 0; ni < 8; ni++) {
            float s0 = cs[ni][0] * SC, s1 = cs[ni][1] * SC;
            float s2 = cs[ni][2] * SC, s3 = cs[ni][3] * SC;
            if (kt == qt) {
                const int colb = kt * 64 + ni * 8 + 2 * t4;
                if (colb     > row0g)     s0 = -1e30f;
                if (colb + 1 > row0g)     s1 = -1e30f;
                if (colb     > row0g + 8) s2 = -1e30f;
                if (colb + 1 > row0g + 8) s3 = -1e30f;
            }
            cs[ni][0] = s0; cs[ni][1] = s1; cs[ni][2] = s2; cs[ni][3] = s3;
            rm0 = fmaxf(rm0, fmaxf(s0, s1));
            rm1 = fmaxf(rm1, fmaxf(s2, s3));
        }
        rm0 = fmaxf(rm0, __shfl_xor_sync(0xffffffffu, rm0, 1));
        rm0 = fmaxf(rm0, __shfl_xor_sync(0xffffffffu, rm0, 2));
        rm1 = fmaxf(rm1, __shfl_xor_sync(0xffffffffu, rm1, 1));
        rm1 = fmaxf(rm1, __shfl_xor_sync(0xffffffffu, rm1, 2));

        const float mt0 = fmaxf(m0, rm0), mt1 = fmaxf(m1, rm1);
        const float corr0 = __expf(m0 - mt0), corr1 = __expf(m1 - mt1);
        m0 = mt0; m1 = mt1;

        // ---- P = exp(S - m), rounded to tf32 so l matches the PV numerator
        float sum0 = 0.0f, sum1 = 0.0f;
        #pragma unroll
        for (int ni = 0; ni < 8; ni++) {
            const int cc = ni * 8 + 2 * t4;
            float p0 = tf32r(__expf(cs[ni][0] - mt0));
            float p1 = tf32r(__expf(cs[ni][1] - mt0));
            float p2 = tf32r(__expf(cs[ni][2] - mt1));
            float p3 = tf32r(__expf(cs[ni][3] - mt1));
            sum0 += p0 + p1; sum1 += p2 + p3;
            Pw0[cc] = p0; Pw0[cc + 1] = p1;
            Pw1[cc] = p2; Pw1[cc + 1] = p3;
        }
        sum0 += __shfl_xor_sync(0xffffffffu, sum0, 1);
        sum0 += __shfl_xor_sync(0xffffffffu, sum0, 2);
        sum1 += __shfl_xor_sync(0xffffffffu, sum1, 1);
        sum1 += __shfl_xor_sync(0xffffffffu, sum1, 2);
        l0 = l0 * corr0 + sum0;
        l1 = l1 * corr1 + sum1;

        #pragma unroll
        for (int ni = 0; ni < 8; ni++) {
            co[ni][0] *= corr0; co[ni][1] *= corr0;
            co[ni][2] *= corr1; co[ni][3] *= corr1;
        }
        __syncwarp();

        // ---- O += P @ V (V accessed transposed: b(n=d, k=key) = Vs[key][d])
        #pragma unroll
        for (int ks = 0; ks < 8; ks++) {
            const int kk = ks * 8 + t4;
            uint32_t a[4];
            a[0] = __float_as_uint(Pw0[kk]);
            a[1] = __float_as_uint(Pw1[kk]);
            a[2] = __float_as_uint(Pw0[kk + 4]);
            a[3] = __float_as_uint(Pw1[kk + 4]);
            #pragma unroll
            for (int ni = 0; ni < 8; ni++) {
                uint32_t bb[2];
                bb[0] = __float_as_uint(VsB[kk * LDV + ni * 8 + g]);
                bb[1] = __float_as_uint(VsB[(kk + 4) * LDV + ni * 8 + g]);
                mma_tf32(co[ni], a, bb);
            }
        }
        __syncwarp();
    }

    // ---- normalize + store
    const float inv0 = 1.0f / l0, inv1 = 1.0f / l1;
    const size_t gr0 = (size_t)(b * TT) + qt * 64 + warp * 16 + g;
    float* Or0 = O + gr0 * DD + h * 64;
    float* Or1 = Or0 + (size_t)8 * DD;
    #pragma unroll
    for (int ni = 0; ni < 8; ni++) {
        const int cc = ni * 8 + 2 * t4;
        *(float2*)(Or0 + cc) = make_float2(co[ni][0] * inv0, co[ni][1] * inv0);
        *(float2*)(Or1 + cc) = make_float2(co[ni][2] * inv1, co[ni][3] * inv1);
    }
}

// ---------------- fused residual-add + LayerNorm ------------------------------
__global__ __launch_bounds__(256) void add_ln_kernel(
    const float* __restrict__ A, const float* __restrict__ Bv,
    const float* __restrict__ g, const float* __restrict__ be,
    float* __restrict__ out)
{
    const int row = blockIdx.x;
    const int tid = threadIdx.x;
    const size_t base = (size_t)row * DD + tid * 4;

    float4 av = *(const float4*)(A + base);
    float4 bv = *(const float4*)(Bv + base);
    float y0 = av.x + bv.x, y1 = av.y + bv.y, y2 = av.z + bv.z, y3 = av.w + bv.w;

    float s  = y0 + y1 + y2 + y3;
    float ss = y0 * y0 + y1 * y1 + y2 * y2 + y3 * y3;

    #pragma unroll
    for (int o = 16; o > 0; o >>= 1) {
        s  += __shfl_xor_sync(0xffffffffu, s, o);
        ss += __shfl_xor_sync(0xffffffffu, ss, o);
    }
    __shared__ float red_s[8], red_ss[8];
    const int wid = tid >> 5;
    if ((tid & 31) == 0) { red_s[wid] = s; red_ss[wid] = ss; }
    __syncthreads();
    float ts = 0.0f, tss = 0.0f;
    #pragma unroll
    for (int w = 0; w < 8; w++) { ts += red_s[w]; tss += red_ss[w]; }

    const float mu   = ts * (1.0f / DD);
    const float var  = tss * (1.0f / DD) - mu * mu;
    const float rstd = rsqrtf(var + 1e-5f);

    float4 gv  = *(const float4*)(g  + tid * 4);
    float4 bev = *(const float4*)(be + tid * 4);
    float4 ov;
    ov.x = (y0 - mu) * rstd * gv.x + bev.x;
    ov.y = (y1 - mu) * rstd * gv.y + bev.y;
    ov.z = (y2 - mu) * rstd * gv.z + bev.z;
    ov.w = (y3 - mu) * rstd * gv.w + bev.w;
    *(float4*)(out + base) = ov;
}

// ---------------- launch ------------------------------------------------------
extern "C" void kernel_launch(void* const* d_in, const int* in_sizes, int n_in,
                              void* d_out, int out_size)
{
    const float* x   = (const float*)d_in[0];
    const float* WQ  = (const float*)d_in[1];
    const float* bQ  = (const float*)d_in[2];
    const float* WK  = (const float*)d_in[3];
    const float* bK  = (const float*)d_in[4];
    const float* WV  = (const float*)d_in[5];
    const float* bV  = (const float*)d_in[6];
    const float* WO  = (const float*)d_in[7];
    const float* bO  = (const float*)d_in[8];
    const float* W1  = (const float*)d_in[9];
    const float* b1  = (const float*)d_in[10];
    const float* W2  = (const float*)d_in[11];
    const float* b2  = (const float*)d_in[12];
    const float* g1  = (const float*)d_in[13];
    const float* be1 = (const float*)d_in[14];
    const float* g2  = (const float*)d_in[15];
    const float* be2 = (const float*)d_in[16];
    float* out = (float*)d_out;

    float *p_q, *p_k, *p_v, *p_attn, *p_proj, *p_x1, *p_ffn1, *p_ffn2;
    cudaGetSymbolAddress((void**)&p_q,    g_q);
    cudaGetSymbolAddress((void**)&p_k,    g_k);
    cudaGetSymbolAddress((void**)&p_v,    g_v);
    cudaGetSymbolAddress((void**)&p_attn, g_attn);
    cudaGetSymbolAddress((void**)&p_proj, g_proj);
    cudaGetSymbolAddress((void**)&p_x1,   g_x1);
    cudaGetSymbolAddress((void**)&p_ffn1, g_ffn1);
    cudaGetSymbolAddress((void**)&p_ffn2, g_ffn2);

    cudaFuncSetAttribute(gemm_tf32_nt<false>,
                         cudaFuncAttributeMaxDynamicSharedMemorySize, GEMM_SMEM);
    cudaFuncSetAttribute(gemm_tf32_nt<true>,
                         cudaFuncAttributeMaxDynamicSharedMemorySize, GEMM_SMEM);
    cudaFuncSetAttribute(attn_mma_kernel,
                         cudaFuncAttributeMaxDynamicSharedMemorySize, ATTN_SMEM);

    const dim3 gD(DD / 128, MM / 128);     // (8, 64)
    const dim3 gF(FFN / 128, MM / 128);    // (32, 64)

    // Q/K/V projections
    gemm_tf32_nt<false><<<gD, 256, GEMM_SMEM>>>(x, WQ, bQ, p_q, MM, DD, DD);
    gemm_tf32_nt<false><<<gD, 256, GEMM_SMEM>>>(x, WK, bK, p_k, MM, DD, DD);
    gemm_tf32_nt<false><<<gD, 256, GEMM_SMEM>>>(x, WV, bV, p_v, MM, DD, DD);

    // causal attention (tensor cores)
    attn_mma_kernel<<<dim3(TT / 64, HH, BB), 128, ATTN_SMEM>>>(p_q, p_k, p_v, p_attn);

    // output projection + LN1
    gemm_tf32_nt<false><<<gD, 256, GEMM_SMEM>>>(p_attn, WO, bO, p_proj, MM, DD, DD);
    add_ln_kernel<<<MM, 256>>>(x, p_proj, g1, be1, p_x1);

    // FFN + LN2
    gemm_tf32_nt<true ><<<gF, 256, GEMM_SMEM>>>(p_x1, W1, b1, p_ffn1, MM, FFN, DD);
    gemm_tf32_nt<false><<<gD, 256, GEMM_SMEM>>>(p_ffn1, W2, b2, p_ffn2, MM, DD, FFN);
    add_ln_kernel<<<MM, 256>>>(p_x1, p_ffn2, g2, be2, out);
}

// round 9
// speedup vs baseline: 4.3923x; 1.1723x over previous
#include <cuda_runtime.h>
#include <cuda_bf16.h>
#include <math_constants.h>
#include <cstdint>

// Problem constants
#define BB 4
#define TT 2048
#define DD 1024
#define HH 16
#define DKK 64
#define FFN 4096
#define MM (BB * TT)      // 8192 rows
#define QKVS (3 * DD)     // fused QKV row stride

// ---------------- scratch (device globals; no runtime allocation) ------------
__device__ float g_xr[MM * DD];                 // x rounded to tf32
__device__ float g_qkv[(size_t)MM * QKVS];      // fused QKV output (tf32-rounded)
__device__ float g_attn[MM * DD];               // attn out (tf32-rounded)
__device__ float g_proj[MM * DD];
__device__ float g_x1[MM * DD];                 // LN1 out fp32 (residual)
__device__ float g_x1r[MM * DD];                // LN1 out tf32-rounded (GEMM A)
__device__ float g_ffn1[(size_t)MM * FFN];      // relu out (tf32-rounded)
__device__ float g_ffn2[MM * DD];
// rounded weights
__device__ float g_wqkv[(size_t)QKVS * DD];     // WQ|WK|WV rounded
__device__ float g_bqkv[QKVS];
__device__ float g_wo[DD * DD];
__device__ float g_w1[(size_t)FFN * DD];
__device__ float g_w2[(size_t)DD * FFN];

// ---------------- helpers -----------------------------------------------------
__device__ __forceinline__ uint32_t f2tf32(float f) {
    uint32_t r;
    asm("cvt.rna.tf32.f32 %0, %1;" : "=r"(r) : "f"(f));
    return r;
}
__device__ __forceinline__ float tf32r(float f) {
    return __uint_as_float(f2tf32(f));
}

__device__ __forceinline__ void cp_async16(uint32_t smem_addr, const void* gptr) {
    asm volatile("cp.async.ca.shared.global [%0], [%1], 16;\n"
                 :: "r"(smem_addr), "l"(gptr));
}
__device__ __forceinline__ void cp_commit() {
    asm volatile("cp.async.commit_group;\n" ::: "memory");
}
__device__ __forceinline__ void cp_wait0() {
    asm volatile("cp.async.wait_group 0;\n" ::: "memory");
}

__device__ __forceinline__ void mma_tf32(float c[4], const uint32_t a[4], const uint32_t b[2]) {
    asm volatile(
        "mma.sync.aligned.m16n8k8.row.col.f32.tf32.tf32.f32 "
        "{%0,%1,%2,%3}, {%4,%5,%6,%7}, {%8,%9}, {%0,%1,%2,%3};\n"
        : "+f"(c[0]), "+f"(c[1]), "+f"(c[2]), "+f"(c[3])
        : "r"(a[0]), "r"(a[1]), "r"(a[2]), "r"(a[3]), "r"(b[0]), "r"(b[1]));
}

// ---------------- rounding copy (fp32 -> tf32-in-fp32) ------------------------
__global__ __launch_bounds__(256) void round_copy_kernel(
    const float* __restrict__ src, float* __restrict__ dst, size_t n4)
{
    const size_t i = (size_t)blockIdx.x * blockDim.x + threadIdx.x;
    const size_t stride = (size_t)gridDim.x * blockDim.x;
    for (size_t j = i; j < n4; j += stride) {
        float4 v = ((const float4*)src)[j];
        v.x = tf32r(v.x); v.y = tf32r(v.y); v.z = tf32r(v.z); v.w = tf32r(v.w);
        ((float4*)dst)[j] = v;
    }
}

// ---------------- TF32 tensor-core GEMM: C = A[M,K] @ W[N,K]^T + bias ---------
// A and W must ALREADY be tf32-rounded (raw bit loads, no in-loop cvt).
constexpr int LDA = 36;
constexpr int STAGE_F = 128 * LDA;
constexpr int GEMM_SMEM = 2 * 2 * STAGE_F * 4;

template <bool RELU, bool ROUND>
__global__ __launch_bounds__(256, 2) void gemm_raw_nt(
    const float* __restrict__ A, const float* __restrict__ W,
    const float* __restrict__ bias, float* __restrict__ C,
    int M, int N, int K)
{
    extern __shared__ float smem[];
    float* As = smem;
    float* Bs = smem + 2 * STAGE_F;

    const int tid  = threadIdx.x;
    const int lane = tid & 31;
    const int wid  = tid >> 5;
    const int warp_m = wid >> 2;
    const int warp_n = wid & 3;
    const int row0 = blockIdx.y * 128;
    const int col0 = blockIdx.x * 128;

    const int lr = tid >> 3;
    const int lc = (tid & 7) * 4;

    const float* gA = A + (size_t)(row0 + lr) * K + lc;
    const float* gW = W + (size_t)(col0 + lr) * K + lc;

    uint32_t sA_base = (uint32_t)__cvta_generic_to_shared(As);
    uint32_t sB_base = (uint32_t)__cvta_generic_to_shared(Bs);

    auto load_stage = [&](int buf, int kiter) {
        const size_t kofs = (size_t)kiter * 32;
        #pragma unroll
        for (int r = 0; r < 4; r++) {
            const int row = lr + r * 32;
            uint32_t so = (uint32_t)((buf * STAGE_F + row * LDA + lc) * 4);
            cp_async16(sA_base + so, gA + (size_t)(r * 32) * K + kofs);
            cp_async16(sB_base + so, gW + (size_t)(r * 32) * K + kofs);
        }
    };

    float c[4][4][4];
    #pragma unroll
    for (int mi = 0; mi < 4; mi++)
        #pragma unroll
        for (int ni = 0; ni < 4; ni++)
            #pragma unroll
            for (int r = 0; r < 4; r++) c[mi][ni][r] = 0.0f;

    const int iters = K / 32;
    load_stage(0, 0);
    cp_commit();

    int buf = 0;
    for (int it = 0; it < iters; it++) {
        cp_wait0();
        __syncthreads();
        if (it + 1 < iters) { load_stage(buf ^ 1, it + 1); cp_commit(); }

        const float* Ab = As + buf * STAGE_F;
        const float* Bb = Bs + buf * STAGE_F;
        const int g  = lane >> 2;
        const int t4 = lane & 3;

        #pragma unroll
        for (int ks = 0; ks < 4; ks++) {
            const int kk = ks * 8 + t4;
            uint32_t a[4][4], b[4][2];
            #pragma unroll
            for (int mi = 0; mi < 4; mi++) {
                const int ar = warp_m * 64 + mi * 16 + g;
                a[mi][0] = __float_as_uint(Ab[ar * LDA + kk]);
                a[mi][1] = __float_as_uint(Ab[(ar + 8) * LDA + kk]);
                a[mi][2] = __float_as_uint(Ab[ar * LDA + kk + 4]);
                a[mi][3] = __float_as_uint(Ab[(ar + 8) * LDA + kk + 4]);
            }
            #pragma unroll
            for (int ni = 0; ni < 4; ni++) {
                const int br = warp_n * 32 + ni * 8 + g;
                b[ni][0] = __float_as_uint(Bb[br * LDA + kk]);
                b[ni][1] = __float_as_uint(Bb[br * LDA + kk + 4]);
            }
            #pragma unroll
            for (int mi = 0; mi < 4; mi++)
                #pragma unroll
                for (int ni = 0; ni < 4; ni++)
                    mma_tf32(c[mi][ni], a[mi], b[ni]);
        }
        __syncthreads();
        buf ^= 1;
    }

    const int g  = lane >> 2;
    const int t4 = lane & 3;
    #pragma unroll
    for (int ni = 0; ni < 4; ni++) {
        const int col = col0 + warp_n * 32 + ni * 8 + t4 * 2;
        const float b0 = bias[col], b1 = bias[col + 1];
        #pragma unroll
        for (int mi = 0; mi < 4; mi++) {
            const int row = row0 + warp_m * 64 + mi * 16 + g;
            float v0 = c[mi][ni][0] + b0;
            float v1 = c[mi][ni][1] + b1;
            float v2 = c[mi][ni][2] + b0;
            float v3 = c[mi][ni][3] + b1;
            if (RELU) {
                v0 = fmaxf(v0, 0.0f); v1 = fmaxf(v1, 0.0f);
                v2 = fmaxf(v2, 0.0f); v3 = fmaxf(v3, 0.0f);
            }
            if (ROUND) {
                v0 = tf32r(v0); v1 = tf32r(v1);
                v2 = tf32r(v2); v3 = tf32r(v3);
            }
            *(float2*)(C + (size_t)row * N + col)       = make_float2(v0, v1);
            *(float2*)(C + (size_t)(row + 8) * N + col) = make_float2(v2, v3);
        }
    }
}

// ---------------- Tensor-core flash attention (causal, tf32 mma) --------------
// Inputs are the fused QKV buffer (row stride 3072), already tf32-rounded.
// Output is tf32-rounded (feeds the WO GEMM as A operand).
constexpr int LDQ = 68;
constexpr int LDV = 72;
constexpr int AQ_OFF = 0;                       // Qs [64][68]
constexpr int AK_OFF = 64 * LDQ;                // Ks [2][64][68]
constexpr int AV_OFF = AK_OFF + 2 * 64 * LDQ;   // Vs [2][64][72]
constexpr int AP_OFF = AV_OFF + 2 * 64 * LDV;   // Ps [64][68]
constexpr int ATTN_SMEM_F = AP_OFF + 64 * LDQ;
constexpr int ATTN_SMEM = ATTN_SMEM_F * 4;

__global__ __launch_bounds__(128, 2) void attn_mma_kernel(
    const float* __restrict__ QKV, float* __restrict__ O)
{
    extern __shared__ float sm[];
    float* Qs = sm + AQ_OFF;
    float* Ps = sm + AP_OFF;

    const int tid  = threadIdx.x;
    const int lane = tid & 31;
    const int warp = tid >> 5;
    const int g    = lane >> 2;
    const int t4   = lane & 3;
    const int qt = blockIdx.x;
    const int h  = blockIdx.y;
    const int b  = blockIdx.z;

    const uint32_t s_base = (uint32_t)__cvta_generic_to_shared(sm);

    // ---- async load Q tile + K/V tile 0
    {
        const float* Qp = QKV + ((size_t)(b * TT + qt * 64)) * QKVS + h * 64;
        #pragma unroll
        for (int i = 0; i < 8; i++) {
            int e = i * 128 + tid;
            int rr = e >> 4;
            int c4 = (e & 15) * 4;
            cp_async16(s_base + (uint32_t)((AQ_OFF + rr * LDQ + c4) * 4),
                       Qp + (size_t)rr * QKVS + c4);
        }
    }
    auto load_kv = [&](int buf, int kt) {
        const float* Kp = QKV + ((size_t)(b * TT + kt * 64)) * QKVS + DD + h * 64;
        const float* Vp = Kp + DD;
        #pragma unroll
        for (int i = 0; i < 8; i++) {
            int e = i * 128 + tid;
            int rr = e >> 4;
            int c4 = (e & 15) * 4;
            cp_async16(s_base + (uint32_t)((AK_OFF + buf * 64 * LDQ + rr * LDQ + c4) * 4),
                       Kp + (size_t)rr * QKVS + c4);
            cp_async16(s_base + (uint32_t)((AV_OFF + buf * 64 * LDV + rr * LDV + c4) * 4),
                       Vp + (size_t)rr * QKVS + c4);
        }
    };
    load_kv(0, 0);
    cp_commit();

    float m0 = -1e30f, m1 = -1e30f, l0 = 0.0f, l1 = 0.0f;
    float co[8][4];
    #pragma unroll
    for (int ni = 0; ni < 8; ni++)
        #pragma unroll
        for (int r = 0; r < 4; r++) co[ni][r] = 0.0f;

    const int row0g = qt * 64 + warp * 16 + g;
    float* Pw0 = Ps + (warp * 16 + g) * LDQ;
    float* Pw1 = Pw0 + 8 * LDQ;
    const float* Qw = Qs + (warp * 16) * LDQ;

    for (int kt = 0; kt <= qt; kt++) {
        const int buf = kt & 1;
        float* KsB = sm + AK_OFF + buf * 64 * LDQ;
        float* VsB = sm + AV_OFF + buf * 64 * LDV;

        cp_wait0();
        __syncthreads();
        if (kt < qt) { load_kv(buf ^ 1, kt + 1); cp_commit(); }

        // ---- S = Q @ K^T (16x64 per warp)
        float cs[8][4];
        #pragma unroll
        for (int ni = 0; ni < 8; ni++)
            #pragma unroll
            for (int r = 0; r < 4; r++) cs[ni][r] = 0.0f;

        #pragma unroll
        for (int ks = 0; ks < 8; ks++) {
            const int kk = ks * 8 + t4;
            uint32_t a[4];
            a[0] = __float_as_uint(Qw[g * LDQ + kk]);
            a[1] = __float_as_uint(Qw[(g + 8) * LDQ + kk]);
            a[2] = __float_as_uint(Qw[g * LDQ + kk + 4]);
            a[3] = __float_as_uint(Qw[(g + 8) * LDQ + kk + 4]);
            #pragma unroll
            for (int ni = 0; ni < 8; ni++) {
                uint32_t bb[2];
                bb[0] = __float_as_uint(KsB[(ni * 8 + g) * LDQ + kk]);
                bb[1] = __float_as_uint(KsB[(ni * 8 + g) * LDQ + kk + 4]);
                mma_tf32(cs[ni], a, bb);
            }
        }

        // ---- scale + causal mask (only diagonal tile)
        const float SC = 0.125f;
        float rm0 = -1e30f, rm1 = -1e30f;
        #pragma unroll
        for (int ni = 0; ni < 8; ni++) {
            float s0 = cs[ni][0] * SC, s1 = cs[ni][1] * SC;
            float s2 = cs[ni][2] * SC, s3 = cs[ni][3] * SC;
            if (kt == qt) {
                const int colb = kt * 64 + ni * 8 + 2 * t4;
                if (colb     > row0g)     s0 = -1e30f;
                if (colb + 1 > row0g)     s1 = -1e30f;
                if (colb     > row0g + 8) s2 = -1e30f;
                if (colb + 1 > row0g + 8) s3 = -1e30f;
            }
            cs[ni][0] = s0; cs[ni][1] = s1; cs[ni][2] = s2; cs[ni][3] = s3;
            rm0 = fmaxf(rm0, fmaxf(s0, s1));
            rm1 = fmaxf(rm1, fmaxf(s2, s3));
        }
        rm0 = fmaxf(rm0, __shfl_xor_sync(0xffffffffu, rm0, 1));
        rm0 = fmaxf(rm0, __shfl_xor_sync(0xffffffffu, rm0, 2));
        rm1 = fmaxf(rm1, __shfl_xor_sync(0xffffffffu, rm1, 1));
        rm1 = fmaxf(rm1, __shfl_xor_sync(0xffffffffu, rm1, 2));

        const float mt0 = fmaxf(m0, rm0), mt1 = fmaxf(m1, rm1);
        const float corr0 = __expf(m0 - mt0), corr1 = __expf(m1 - mt1);
        m0 = mt0; m1 = mt1;

        // ---- P = exp(S - m) rounded to tf32; l sums the rounded values
        float sum0 = 0.0f, sum1 = 0.0f;
        #pragma unroll
        for (int ni = 0; ni < 8; ni++) {
            const int cc = ni * 8 + 2 * t4;
            float p0 = tf32r(__expf(cs[ni][0] - mt0));
            float p1 = tf32r(__expf(cs[ni][1] - mt0));
            float p2 = tf32r(__expf(cs[ni][2] - mt1));
            float p3 = tf32r(__expf(cs[ni][3] - mt1));
            sum0 += p0 + p1; sum1 += p2 + p3;
            Pw0[cc] = p0; Pw0[cc + 1] = p1;
            Pw1[cc] = p2; Pw1[cc + 1] = p3;
        }
        sum0 += __shfl_xor_sync(0xffffffffu, sum0, 1);
        sum0 += __shfl_xor_sync(0xffffffffu, sum0, 2);
        sum1 += __shfl_xor_sync(0xffffffffu, sum1, 1);
        sum1 += __shfl_xor_sync(0xffffffffu, sum1, 2);
        l0 = l0 * corr0 + sum0;
        l1 = l1 * corr1 + sum1;

        #pragma unroll
        for (int ni = 0; ni < 8; ni++) {
            co[ni][0] *= corr0; co[ni][1] *= corr0;
            co[ni][2] *= corr1; co[ni][3] *= corr1;
        }
        __syncwarp();

        // ---- O += P @ V
        #pragma unroll
        for (int ks = 0; ks < 8; ks++) {
            const int kk = ks * 8 + t4;
            uint32_t a[4];
            a[0] = __float_as_uint(Pw0[kk]);
            a[1] = __float_as_uint(Pw1[kk]);
            a[2] = __float_as_uint(Pw0[kk + 4]);
            a[3] = __float_as_uint(Pw1[kk + 4]);
            #pragma unroll
            for (int ni = 0; ni < 8; ni++) {
                uint32_t bb[2];
                bb[0] = __float_as_uint(VsB[kk * LDV + ni * 8 + g]);
                bb[1] = __float_as_uint(VsB[(kk + 4) * LDV + ni * 8 + g]);
                mma_tf32(co[ni], a, bb);
            }
        }
        __syncwarp();
    }

    // ---- normalize + round (feeds WO GEMM) + store
    const float inv0 = 1.0f / l0, inv1 = 1.0f / l1;
    const size_t gr0 = (size_t)(b * TT) + qt * 64 + warp * 16 + g;
    float* Or0 = O + gr0 * DD + h * 64;
    float* Or1 = Or0 + (size_t)8 * DD;
    #pragma unroll
    for (int ni = 0; ni < 8; ni++) {
        const int cc = ni * 8 + 2 * t4;
        *(float2*)(Or0 + cc) = make_float2(tf32r(co[ni][0] * inv0), tf32r(co[ni][1] * inv0));
        *(float2*)(Or1 + cc) = make_float2(tf32r(co[ni][2] * inv1), tf32r(co[ni][3] * inv1));
    }
}

// ---------------- fused residual-add + LayerNorm ------------------------------
// Optionally also writes a tf32-rounded copy (GEMM A operand).
template <bool WRITE_R>
__global__ __launch_bounds__(256) void add_ln_kernel(
    const float* __restrict__ A, const float* __restrict__ Bv,
    const float* __restrict__ g, const float* __restrict__ be,
    float* __restrict__ out, float* __restrict__ out_r)
{
    const int row = blockIdx.x;
    const int tid = threadIdx.x;
    const size_t base = (size_t)row * DD + tid * 4;

    float4 av = *(const float4*)(A + base);
    float4 bv = *(const float4*)(Bv + base);
    float y0 = av.x + bv.x, y1 = av.y + bv.y, y2 = av.z + bv.z, y3 = av.w + bv.w;

    float s  = y0 + y1 + y2 + y3;
    float ss = y0 * y0 + y1 * y1 + y2 * y2 + y3 * y3;

    #pragma unroll
    for (int o = 16; o > 0; o >>= 1) {
        s  += __shfl_xor_sync(0xffffffffu, s, o);
        ss += __shfl_xor_sync(0xffffffffu, ss, o);
    }
    __shared__ float red_s[8], red_ss[8];
    const int wid = tid >> 5;
    if ((tid & 31) == 0) { red_s[wid] = s; red_ss[wid] = ss; }
    __syncthreads();
    float ts = 0.0f, tss = 0.0f;
    #pragma unroll
    for (int w = 0; w < 8; w++) { ts += red_s[w]; tss += red_ss[w]; }

    const float mu   = ts * (1.0f / DD);
    const float var  = tss * (1.0f / DD) - mu * mu;
    const float rstd = rsqrtf(var + 1e-5f);

    float4 gv  = *(const float4*)(g  + tid * 4);
    float4 bev = *(const float4*)(be + tid * 4);
    float4 ov;
    ov.x = (y0 - mu) * rstd * gv.x + bev.x;
    ov.y = (y1 - mu) * rstd * gv.y + bev.y;
    ov.z = (y2 - mu) * rstd * gv.z + bev.z;
    ov.w = (y3 - mu) * rstd * gv.w + bev.w;
    *(float4*)(out + base) = ov;
    if (WRITE_R) {
        float4 rv;
        rv.x = tf32r(ov.x); rv.y = tf32r(ov.y);
        rv.z = tf32r(ov.z); rv.w = tf32r(ov.w);
        *(float4*)(out_r + base) = rv;
    }
}

// ---------------- launch ------------------------------------------------------
extern "C" void kernel_launch(void* const* d_in, const int* in_sizes, int n_in,
                              void* d_out, int out_size)
{
    const float* x   = (const float*)d_in[0];
    const float* WQ  = (const float*)d_in[1];
    const float* bQ  = (const float*)d_in[2];
    const float* WK  = (const float*)d_in[3];
    const float* bK  = (const float*)d_in[4];
    const float* WV  = (const float*)d_in[5];
    const float* bV  = (const float*)d_in[6];
    const float* WO  = (const float*)d_in[7];
    const float* bO  = (const float*)d_in[8];
    const float* W1  = (const float*)d_in[9];
    const float* b1  = (const float*)d_in[10];
    const float* W2  = (const float*)d_in[11];
    const float* b2  = (const float*)d_in[12];
    const float* g1  = (const float*)d_in[13];
    const float* be1 = (const float*)d_in[14];
    const float* g2  = (const float*)d_in[15];
    const float* be2 = (const float*)d_in[16];
    float* out = (float*)d_out;

    float *p_xr, *p_qkv, *p_attn, *p_proj, *p_x1, *p_x1r, *p_ffn1, *p_ffn2;
    float *p_wqkv, *p_bqkv, *p_wo, *p_w1, *p_w2;
    cudaGetSymbolAddress((void**)&p_xr,   g_xr);
    cudaGetSymbolAddress((void**)&p_qkv,  g_qkv);
    cudaGetSymbolAddress((void**)&p_attn, g_attn);
    cudaGetSymbolAddress((void**)&p_proj, g_proj);
    cudaGetSymbolAddress((void**)&p_x1,   g_x1);
    cudaGetSymbolAddress((void**)&p_x1r,  g_x1r);
    cudaGetSymbolAddress((void**)&p_ffn1, g_ffn1);
    cudaGetSymbolAddress((void**)&p_ffn2, g_ffn2);
    cudaGetSymbolAddress((void**)&p_wqkv, g_wqkv);
    cudaGetSymbolAddress((void**)&p_bqkv, g_bqkv);
    cudaGetSymbolAddress((void**)&p_wo,   g_wo);
    cudaGetSymbolAddress((void**)&p_w1,   g_w1);
    cudaGetSymbolAddress((void**)&p_w2,   g_w2);

    cudaFuncSetAttribute(gemm_raw_nt<false, false>,
                         cudaFuncAttributeMaxDynamicSharedMemorySize, GEMM_SMEM);
    cudaFuncSetAttribute(gemm_raw_nt<false, true>,
                         cudaFuncAttributeMaxDynamicSharedMemorySize, GEMM_SMEM);
    cudaFuncSetAttribute(gemm_raw_nt<true, true>,
                         cudaFuncAttributeMaxDynamicSharedMemorySize, GEMM_SMEM);
    cudaFuncSetAttribute(attn_mma_kernel,
                         cudaFuncAttributeMaxDynamicSharedMemorySize, ATTN_SMEM);

    const int RB = 1024;   // blocks for round_copy

    // ---- pre-round weights (into fused/scratch copies) + x, concat biases
    round_copy_kernel<<<RB, 256>>>(WQ, p_wqkv,                    (size_t)DD * DD / 4);
    round_copy_kernel<<<RB, 256>>>(WK, p_wqkv + (size_t)DD * DD,  (size_t)DD * DD / 4);
    round_copy_kernel<<<RB, 256>>>(WV, p_wqkv + (size_t)2 * DD * DD, (size_t)DD * DD / 4);
    round_copy_kernel<<<RB, 256>>>(WO, p_wo, (size_t)DD * DD / 4);
    round_copy_kernel<<<RB, 256>>>(W1, p_w1, (size_t)FFN * DD / 4);
    round_copy_kernel<<<RB, 256>>>(W2, p_w2, (size_t)DD * FFN / 4);
    round_copy_kernel<<<RB, 256>>>(x,  p_xr, (size_t)MM * DD / 4);
    cudaMemcpyAsync(p_bqkv,          bQ, DD * sizeof(float), cudaMemcpyDeviceToDevice);
    cudaMemcpyAsync(p_bqkv + DD,     bK, DD * sizeof(float), cudaMemcpyDeviceToDevice);
    cudaMemcpyAsync(p_bqkv + 2 * DD, bV, DD * sizeof(float), cudaMemcpyDeviceToDevice);

    const dim3 gQKV(QKVS / 128, MM / 128);   // (24, 64)
    const dim3 gD(DD / 128, MM / 128);       // (8, 64)
    const dim3 gF(FFN / 128, MM / 128);      // (32, 64)

    // fused QKV projection (output tf32-rounded for attention)
    gemm_raw_nt<false, true><<<gQKV, 256, GEMM_SMEM>>>(p_xr, p_wqkv, p_bqkv, p_qkv, MM, QKVS, DD);

    // causal attention (tensor cores); output tf32-rounded
    attn_mma_kernel<<<dim3(TT / 64, HH, BB), 128, ATTN_SMEM>>>(p_qkv, p_attn);

    // output projection + LN1 (LN1 writes fp32 + rounded copy)
    gemm_raw_nt<false, false><<<gD, 256, GEMM_SMEM>>>(p_attn, p_wo, bO, p_proj, MM, DD, DD);
    add_ln_kernel<true><<<MM, 256>>>(x, p_proj, g1, be1, p_x1, p_x1r);

    // FFN + LN2
    gemm_raw_nt<true, true><<<gF, 256, GEMM_SMEM>>>(p_x1r, p_w1, b1, p_ffn1, MM, FFN, DD);
    gemm_raw_nt<false, false><<<gD, 256, GEMM_SMEM>>>(p_ffn1, p_w2, b2, p_ffn2, MM, DD, FFN);
    add_ln_kernel<false><<<MM, 256>>>(p_x1, p_ffn2, g2, be2, out, nullptr);
}

// round 11
// speedup vs baseline: 4.4957x; 1.0235x over previous
#include <cuda_runtime.h>
#include <cuda_bf16.h>
#include <math_constants.h>
#include <cstdint>

// Problem constants
#define BB 4
#define TT 2048
#define DD 1024
#define HH 16
#define DKK 64
#define FFN 4096
#define MM (BB * TT)      // 8192 rows
#define QKVS (3 * DD)     // fused QKV row stride

// ---------------- scratch (device globals; no runtime allocation) ------------
__device__ float g_xr[MM * DD];                 // x, tf32-rounded, K-permuted
__device__ float g_qkv[(size_t)MM * QKVS];      // QKV out (rounded, NORMAL layout)
__device__ float g_attn[MM * DD];               // attn out (rounded, PERMUTED)
__device__ float g_proj[MM * DD];
__device__ float g_x1[MM * DD];                 // LN1 fp32 residual
__device__ float g_x1r[MM * DD];                // LN1 rounded, PERMUTED
__device__ float g_ffn1[(size_t)MM * FFN];      // relu out (rounded, PERMUTED)
__device__ float g_ffn2[MM * DD];
// rounded + permuted weights
__device__ float g_wqkv[(size_t)QKVS * DD];
__device__ float g_bqkv[QKVS];
__device__ float g_wo[DD * DD];
__device__ float g_w1[(size_t)FFN * DD];
__device__ float g_w2[(size_t)DD * FFN];

// ---------------- helpers -----------------------------------------------------
__device__ __forceinline__ uint32_t f2tf32(float f) {
    uint32_t r;
    asm("cvt.rna.tf32.f32 %0, %1;" : "=r"(r) : "f"(f));
    return r;
}
__device__ __forceinline__ float tf32r(float f) {
    return __uint_as_float(f2tf32(f));
}
__device__ __forceinline__ void cp_async16(uint32_t smem_addr, const void* gptr) {
    asm volatile("cp.async.ca.shared.global [%0], [%1], 16;\n"
                 :: "r"(smem_addr), "l"(gptr));
}
__device__ __forceinline__ void cp_commit() {
    asm volatile("cp.async.commit_group;\n" ::: "memory");
}
template<int N>
__device__ __forceinline__ void cp_wait_group() {
    asm volatile("cp.async.wait_group %0;\n" :: "n"(N) : "memory");
}
__device__ __forceinline__ void cp_wait0() { cp_wait_group<0>(); }

__device__ __forceinline__ void mma_tf32(float c[4], const uint32_t a[4], const uint32_t b[2]) {
    asm volatile(
        "mma.sync.aligned.m16n8k8.row.col.f32.tf32.tf32.f32 "
        "{%0,%1,%2,%3}, {%4,%5,%6,%7}, {%8,%9}, {%0,%1,%2,%3};\n"
        : "+f"(c[0]), "+f"(c[1]), "+f"(c[2]), "+f"(c[3])
        : "r"(a[0]), "r"(a[1]), "r"(a[2]), "r"(a[3]), "r"(b[0]), "r"(b[1]));
}

// K-pair permutation within each 8-float group: k=j -> 2j (j<4), 2j-7 (j>=4)
// so fragment pair (t4, t4+4) is adjacent (2t4, 2t4+1).
__host__ __device__ __forceinline__ int perm8(int j)  { return j < 4 ? 2 * j : 2 * j - 7; }
__device__ __forceinline__ int inv8(int c)            { return (c & 1) ? (c >> 1) + 4 : (c >> 1); }

// ---------------- rounding + permuting copy -----------------------------------
// dst[row][c] = tf32r(src[row][(c&~7) | inv8(c&7)])  (K-chunk permuted layout)
__global__ __launch_bounds__(256) void round_perm_kernel(
    const float* __restrict__ src, float* __restrict__ dst, int K, size_t n4)
{
    const size_t i = (size_t)blockIdx.x * blockDim.x + threadIdx.x;
    const size_t stride = (size_t)gridDim.x * blockDim.x;
    const int K4 = K / 4;
    for (size_t j = i; j < n4; j += stride) {
        const size_t row = j / K4;
        const int dc = (int)(j % K4) * 4;
        const float* srow = src + row * K;
        float4 v;
        v.x = tf32r(srow[(dc & ~7)       | inv8(dc & 7)]);
        v.y = tf32r(srow[((dc+1) & ~7)   | inv8((dc+1) & 7)]);
        v.z = tf32r(srow[((dc+2) & ~7)   | inv8((dc+2) & 7)]);
        v.w = tf32r(srow[((dc+3) & ~7)   | inv8((dc+3) & 7)]);
        *(float4*)(dst + row * K + dc) = v;
    }
}

// ---------------- TF32 mma.sync GEMM, permuted operands -----------------------
// C[M,N] = A[M,K] @ W[N,K]^T + bias. A and W in rounded+permuted layout.
// CTA 128x128x32, 4 warps (2Mx2N), warp tile 64x64. 3-stage cp.async.
// smem: row stride 32 floats, swizzle col^=(row&3)*8 -> conflict-free LDS.64.
constexpr int GSTAGE_F = 2 * 128 * 32;            // A+B floats per stage
constexpr int GSTAGES  = 3;
constexpr int GEMM_SMEM = GSTAGES * GSTAGE_F * 4; // 98304 B

template <bool RELU, bool ROUND, bool PERM>
__global__ __launch_bounds__(128, 2) void gemm_mma(
    const float* __restrict__ A, const float* __restrict__ W,
    const float* __restrict__ bias, float* __restrict__ C,
    int M, int N, int K)
{
    extern __shared__ float smem[];
    const uint32_t sbase = (uint32_t)__cvta_generic_to_shared(smem);

    const int tid  = threadIdx.x;
    const int lane = tid & 31;
    const int wid  = tid >> 5;
    const int warp_m = wid >> 1;      // 0..1
    const int warp_n = wid & 1;       // 0..1
    const int g  = lane >> 2;         // 0..7
    const int t4 = lane & 3;          // 0..3
    const int row0 = blockIdx.y * 128;
    const int col0 = blockIdx.x * 128;

    const float* gA = A + (size_t)row0 * K;
    const float* gW = W + (size_t)col0 * K;

    // loader: 128 rows x 8 float4-groups each for A and B; 128 threads
    auto load_chunk = [&](int s, int c) {
        const uint32_t ab = sbase + (uint32_t)(s * GSTAGE_F) * 4;
        const uint32_t bb = ab + 128 * 32 * 4;
        const size_t kofs = (size_t)c * 32;
        #pragma unroll
        for (int i = 0; i < 8; i++) {
            int e = i * 128 + tid;
            int r = e >> 3;
            int cg = e & 7;
            uint32_t so = (uint32_t)r * 128 + (((uint32_t)cg * 16) ^ (((uint32_t)r & 3) * 32));
            cp_async16(ab + so, gA + (size_t)r * K + kofs + cg * 4);
            cp_async16(bb + so, gW + (size_t)r * K + kofs + cg * 4);
        }
        cp_commit();
    };

    float acc[4][8][4];
    #pragma unroll
    for (int mi = 0; mi < 4; mi++)
        #pragma unroll
        for (int ni = 0; ni < 8; ni++)
            #pragma unroll
            for (int r = 0; r < 4; r++) acc[mi][ni][r] = 0.0f;

    const int nc = K / 32;
    load_chunk(0, 0);
    if (nc > 1) load_chunk(1, 1);

    for (int c = 0; c < nc; c++) {
        if (c + 1 < nc) cp_wait_group<1>(); else cp_wait_group<0>();
        __syncthreads();
        if (c + 2 < nc) load_chunk((c + 2) % 3, c + 2);

        const float* Ab = smem + (c % 3) * GSTAGE_F;
        const float* Bb = Ab + 128 * 32;

        #pragma unroll
        for (int ks = 0; ks < 4; ks++) {
            const int cA = (8 * ks + 2 * t4) ^ (8 * (g & 3));
            uint32_t a[4][4], b[8][2];
            #pragma unroll
            for (int mi = 0; mi < 4; mi++) {
                const int ar = warp_m * 64 + mi * 16 + g;
                float2 p1 = *(const float2*)&Ab[ar * 32 + cA];
                float2 p2 = *(const float2*)&Ab[(ar + 8) * 32 + cA];
                a[mi][0] = __float_as_uint(p1.x);
                a[mi][1] = __float_as_uint(p2.x);
                a[mi][2] = __float_as_uint(p1.y);
                a[mi][3] = __float_as_uint(p2.y);
            }
            #pragma unroll
            for (int ni = 0; ni < 8; ni++) {
                const int br = warp_n * 64 + ni * 8 + g;
                float2 p = *(const float2*)&Bb[br * 32 + cA];
                b[ni][0] = __float_as_uint(p.x);
                b[ni][1] = __float_as_uint(p.y);
            }
            #pragma unroll
            for (int mi = 0; mi < 4; mi++)
                #pragma unroll
                for (int ni = 0; ni < 8; ni++)
                    mma_tf32(acc[mi][ni], a[mi], b[ni]);
        }
        __syncthreads();
    }

    // ---- epilogue ----
    #pragma unroll
    for (int ni = 0; ni < 8; ni++) {
        const int colL = warp_n * 64 + ni * 8 + 2 * t4;   // local col, even
        const int gcol = col0 + colL;
        const float b0 = bias[gcol], b1 = bias[gcol + 1];
        #pragma unroll
        for (int mi = 0; mi < 4; mi++) {
            const int row = row0 + warp_m * 64 + mi * 16 + g;
            float v0 = acc[mi][ni][0] + b0;
            float v1 = acc[mi][ni][1] + b1;
            float v2 = acc[mi][ni][2] + b0;
            float v3 = acc[mi][ni][3] + b1;
            if (RELU) {
                v0 = fmaxf(v0, 0.0f); v1 = fmaxf(v1, 0.0f);
                v2 = fmaxf(v2, 0.0f); v3 = fmaxf(v3, 0.0f);
            }
            if (ROUND) {
                v0 = tf32r(v0); v1 = tf32r(v1); v2 = tf32r(v2); v3 = tf32r(v3);
            }
            float* cr0 = C + (size_t)row * N;
            float* cr1 = cr0 + (size_t)8 * N;
            if (PERM) {
                const int base7 = colL & ~7;
                const int j = colL & 7;                    // 2*t4
                const int p0 = col0 + (base7 | perm8(j));
                const int p1 = col0 + (base7 | perm8(j + 1));
                cr0[p0] = v0; cr0[p1] = v1;
                cr1[p0] = v2; cr1[p1] = v3;
            } else {
                *(float2*)(cr0 + gcol) = make_float2(v0, v1);
                *(float2*)(cr1 + gcol) = make_float2(v2, v3);
            }
        }
    }
}

// ---------------- Tensor-core flash attention (causal, tf32 mma.sync) ---------
// Reads fused QKV (NORMAL layout, rounded). Writes PERMUTED rounded output.
constexpr int LDQ = 68;
constexpr int LDV = 72;
constexpr int AQ_OFF = 0;
constexpr int AK_OFF = 64 * LDQ;
constexpr int AV_OFF = AK_OFF + 2 * 64 * LDQ;
constexpr int AP_OFF = AV_OFF + 2 * 64 * LDV;
constexpr int ATTN_SMEM_F = AP_OFF + 64 * LDQ;
constexpr int ATTN_SMEM = ATTN_SMEM_F * 4;

__global__ __launch_bounds__(128, 2) void attn_mma_kernel(
    const float* __restrict__ QKV, float* __restrict__ O)
{
    extern __shared__ float sm[];
    float* Qs = sm + AQ_OFF;
    float* Ps = sm + AP_OFF;

    const int tid  = threadIdx.x;
    const int lane = tid & 31;
    const int warp = tid >> 5;
    const int g    = lane >> 2;
    const int t4   = lane & 3;
    const int qt = blockIdx.x;
    const int h  = blockIdx.y;
    const int b  = blockIdx.z;

    const uint32_t s_base = (uint32_t)__cvta_generic_to_shared(sm);

    {
        const float* Qp = QKV + ((size_t)(b * TT + qt * 64)) * QKVS + h * 64;
        #pragma unroll
        for (int i = 0; i < 8; i++) {
            int e = i * 128 + tid;
            int rr = e >> 4;
            int c4 = (e & 15) * 4;
            cp_async16(s_base + (uint32_t)((AQ_OFF + rr * LDQ + c4) * 4),
                       Qp + (size_t)rr * QKVS + c4);
        }
    }
    auto load_kv = [&](int buf, int kt) {
        const float* Kp = QKV + ((size_t)(b * TT + kt * 64)) * QKVS + DD + h * 64;
        const float* Vp = Kp + DD;
        #pragma unroll
        for (int i = 0; i < 8; i++) {
            int e = i * 128 + tid;
            int rr = e >> 4;
            int c4 = (e & 15) * 4;
            cp_async16(s_base + (uint32_t)((AK_OFF + buf * 64 * LDQ + rr * LDQ + c4) * 4),
                       Kp + (size_t)rr * QKVS + c4);
            cp_async16(s_base + (uint32_t)((AV_OFF + buf * 64 * LDV + rr * LDV + c4) * 4),
                       Vp + (size_t)rr * QKVS + c4);
        }
    };
    load_kv(0, 0);
    cp_commit();

    float m0 = -1e30f, m1 = -1e30f, l0 = 0.0f, l1 = 0.0f;
    float co[8][4];
    #pragma unroll
    for (int ni = 0; ni < 8; ni++)
        #pragma unroll
        for (int r = 0; r < 4; r++) co[ni][r] = 0.0f;

    const int row0g = qt * 64 + warp * 16 + g;
    float* Pw0 = Ps + (warp * 16 + g) * LDQ;
    float* Pw1 = Pw0 + 8 * LDQ;
    const float* Qw = Qs + (warp * 16) * LDQ;

    for (int kt = 0; kt <= qt; kt++) {
        const int buf = kt & 1;
        float* KsB = sm + AK_OFF + buf * 64 * LDQ;
        float* VsB = sm + AV_OFF + buf * 64 * LDV;

        cp_wait0();
        __syncthreads();
        if (kt < qt) { load_kv(buf ^ 1, kt + 1); cp_commit(); }

        float cs[8][4];
        #pragma unroll
        for (int ni = 0; ni < 8; ni++)
            #pragma unroll
            for (int r = 0; r < 4; r++) cs[ni][r] = 0.0f;

        #pragma unroll
        for (int ks = 0; ks < 8; ks++) {
            const int kk = ks * 8 + t4;
            uint32_t a[4];
            a[0] = __float_as_uint(Qw[g * LDQ + kk]);
            a[1] = __float_as_uint(Qw[(g + 8) * LDQ + kk]);
            a[2] = __float_as_uint(Qw[g * LDQ + kk + 4]);
            a[3] = __float_as_uint(Qw[(g + 8) * LDQ + kk + 4]);
            #pragma unroll
            for (int ni = 0; ni < 8; ni++) {
                uint32_t bb[2];
                bb[0] = __float_as_uint(KsB[(ni * 8 + g) * LDQ + kk]);
                bb[1] = __float_as_uint(KsB[(ni * 8 + g) * LDQ + kk + 4]);
                mma_tf32(cs[ni], a, bb);
            }
        }

        const float SC = 0.125f;
        float rm0 = -1e30f, rm1 = -1e30f;
        #pragma unroll
        for (int ni = 0; ni < 8; ni++) {
            float s0 = cs[ni][0] * SC, s1 = cs[ni][1] * SC;
            float s2 = cs[ni][2] * SC, s3 = cs[ni][3] * SC;
            if (kt == qt) {
                const int colb = kt * 64 + ni * 8 + 2 * t4;
                if (colb     > row0g)     s0 = -1e30f;
                if (colb + 1 > row0g)     s1 = -1e30f;
                if (colb     > row0g + 8) s2 = -1e30f;
                if (colb + 1 > row0g + 8) s3 = -1e30f;
            }
            cs[ni][0] = s0; cs[ni][1] = s1; cs[ni][2] = s2; cs[ni][3] = s3;
            rm0 = fmaxf(rm0, fmaxf(s0, s1));
            rm1 = fmaxf(rm1, fmaxf(s2, s3));
        }
        rm0 = fmaxf(rm0, __shfl_xor_sync(0xffffffffu, rm0, 1));
        rm0 = fmaxf(rm0, __shfl_xor_sync(0xffffffffu, rm0, 2));
        rm1 = fmaxf(rm1, __shfl_xor_sync(0xffffffffu, rm1, 1));
        rm1 = fmaxf(rm1, __shfl_xor_sync(0xffffffffu, rm1, 2));

        const float mt0 = fmaxf(m0, rm0), mt1 = fmaxf(m1, rm1);
        const float corr0 = __expf(m0 - mt0), corr1 = __expf(m1 - mt1);
        m0 = mt0; m1 = mt1;

        float sum0 = 0.0f, sum1 = 0.0f;
        #pragma unroll
        for (int ni = 0; ni < 8; ni++) {
            const int cc = ni * 8 + 2 * t4;
            float p0 = tf32r(__expf(cs[ni][0] - mt0));
            float p1 = tf32r(__expf(cs[ni][1] - mt0));
            float p2 = tf32r(__expf(cs[ni][2] - mt1));
            float p3 = tf32r(__expf(cs[ni][3] - mt1));
            sum0 += p0 + p1; sum1 += p2 + p3;
            Pw0[cc] = p0; Pw0[cc + 1] = p1;
            Pw1[cc] = p2; Pw1[cc + 1] = p3;
        }
        sum0 += __shfl_xor_sync(0xffffffffu, sum0, 1);
        sum0 += __shfl_xor_sync(0xffffffffu, sum0, 2);
        sum1 += __shfl_xor_sync(0xffffffffu, sum1, 1);
        sum1 += __shfl_xor_sync(0xffffffffu, sum1, 2);
        l0 = l0 * corr0 + sum0;
        l1 = l1 * corr1 + sum1;

        #pragma unroll
        for (int ni = 0; ni < 8; ni++) {
            co[ni][0] *= corr0; co[ni][1] *= corr0;
            co[ni][2] *= corr1; co[ni][3] *= corr1;
        }
        __syncwarp();

        #pragma unroll
        for (int ks = 0; ks < 8; ks++) {
            const int kk = ks * 8 + t4;
            uint32_t a[4];
            a[0] = __float_as_uint(Pw0[kk]);
            a[1] = __float_as_uint(Pw1[kk]);
            a[2] = __float_as_uint(Pw0[kk + 4]);
            a[3] = __float_as_uint(Pw1[kk + 4]);
            #pragma unroll
            for (int ni = 0; ni < 8; ni++) {
                uint32_t bb[2];
                bb[0] = __float_as_uint(VsB[kk * LDV + ni * 8 + g]);
                bb[1] = __float_as_uint(VsB[(kk + 4) * LDV + ni * 8 + g]);
                mma_tf32(co[ni], a, bb);
            }
        }
        __syncwarp();
    }

    // ---- normalize + round + PERMUTED store (feeds WO GEMM) ----
    const float inv0 = 1.0f / l0, inv1 = 1.0f / l1;
    const size_t gr0 = (size_t)(b * TT) + qt * 64 + warp * 16 + g;
    float* Or0 = O + gr0 * DD + h * 64;
    float* Or1 = Or0 + (size_t)8 * DD;
    #pragma unroll
    for (int ni = 0; ni < 8; ni++) {
        const int cc = ni * 8 + 2 * t4;
        const int base7 = cc & ~7;
        const int p0 = base7 | perm8(cc & 7);
        const int p1 = base7 | perm8((cc & 7) + 1);
        Or0[p0] = tf32r(co[ni][0] * inv0);
        Or0[p1] = tf32r(co[ni][1] * inv0);
        Or1[p0] = tf32r(co[ni][2] * inv1);
        Or1[p1] = tf32r(co[ni][3] * inv1);
    }
}

// ---------------- fused residual-add + LayerNorm ------------------------------
// WRITE_R: also writes tf32-rounded PERMUTED copy (next GEMM's A operand).
template <bool WRITE_R>
__global__ __launch_bounds__(256) void add_ln_kernel(
    const float* __restrict__ A, const float* __restrict__ Bv,
    const float* __restrict__ g, const float* __restrict__ be,
    float* __restrict__ out, float* __restrict__ out_r)
{
    const int row = blockIdx.x;
    const int tid = threadIdx.x;
    const size_t base = (size_t)row * DD + tid * 4;

    float4 av = *(const float4*)(A + base);
    float4 bv = *(const float4*)(Bv + base);
    float y0 = av.x + bv.x, y1 = av.y + bv.y, y2 = av.z + bv.z, y3 = av.w + bv.w;

    float s  = y0 + y1 + y2 + y3;
    float ss = y0 * y0 + y1 * y1 + y2 * y2 + y3 * y3;

    #pragma unroll
    for (int o = 16; o > 0; o >>= 1) {
        s  += __shfl_xor_sync(0xffffffffu, s, o);
        ss += __shfl_xor_sync(0xffffffffu, ss, o);
    }
    __shared__ float red_s[8], red_ss[8];
    const int wid = tid >> 5;
    if ((tid & 31) == 0) { red_s[wid] = s; red_ss[wid] = ss; }
    __syncthreads();
    float ts = 0.0f, tss = 0.0f;
    #pragma unroll
    for (int w = 0; w < 8; w++) { ts += red_s[w]; tss += red_ss[w]; }

    const float mu   = ts * (1.0f / DD);
    const float var  = tss * (1.0f / DD) - mu * mu;
    const float rstd = rsqrtf(var + 1e-5f);

    float4 gv  = *(const float4*)(g  + tid * 4);
    float4 bev = *(const float4*)(be + tid * 4);
    float4 ov;
    ov.x = (y0 - mu) * rstd * gv.x + bev.x;
    ov.y = (y1 - mu) * rstd * gv.y + bev.y;
    ov.z = (y2 - mu) * rstd * gv.z + bev.z;
    ov.w = (y3 - mu) * rstd * gv.w + bev.w;
    *(float4*)(out + base) = ov;
    if (WRITE_R) {
        const int c0 = tid * 4;
        float* orow = out_r + (size_t)row * DD;
        const float vv[4] = { tf32r(ov.x), tf32r(ov.y), tf32r(ov.z), tf32r(ov.w) };
        #pragma unroll
        for (int i = 0; i < 4; i++) {
            const int c = c0 + i;
            orow[(c & ~7) | perm8(c & 7)] = vv[i];
        }
    }
}

// ---------------- launch ------------------------------------------------------
extern "C" void kernel_launch(void* const* d_in, const int* in_sizes, int n_in,
                              void* d_out, int out_size)
{
    const float* x   = (const float*)d_in[0];
    const float* WQ  = (const float*)d_in[1];
    const float* bQ  = (const float*)d_in[2];
    const float* WK  = (const float*)d_in[3];
    const float* bK  = (const float*)d_in[4];
    const float* WV  = (const float*)d_in[5];
    const float* bV  = (const float*)d_in[6];
    const float* WO  = (const float*)d_in[7];
    const float* bO  = (const float*)d_in[8];
    const float* W1  = (const float*)d_in[9];
    const float* b1  = (const float*)d_in[10];
    const float* W2  = (const float*)d_in[11];
    const float* b2  = (const float*)d_in[12];
    const float* g1  = (const float*)d_in[13];
    const float* be1 = (const float*)d_in[14];
    const float* g2  = (const float*)d_in[15];
    const float* be2 = (const float*)d_in[16];
    float* out = (float*)d_out;

    float *p_xr, *p_qkv, *p_attn, *p_proj, *p_x1, *p_x1r, *p_ffn1, *p_ffn2;
    float *p_wqkv, *p_bqkv, *p_wo, *p_w1, *p_w2;
    cudaGetSymbolAddress((void**)&p_xr,   g_xr);
    cudaGetSymbolAddress((void**)&p_qkv,  g_qkv);
    cudaGetSymbolAddress((void**)&p_attn, g_attn);
    cudaGetSymbolAddress((void**)&p_proj, g_proj);
    cudaGetSymbolAddress((void**)&p_x1,   g_x1);
    cudaGetSymbolAddress((void**)&p_x1r,  g_x1r);
    cudaGetSymbolAddress((void**)&p_ffn1, g_ffn1);
    cudaGetSymbolAddress((void**)&p_ffn2, g_ffn2);
    cudaGetSymbolAddress((void**)&p_wqkv, g_wqkv);
    cudaGetSymbolAddress((void**)&p_bqkv, g_bqkv);
    cudaGetSymbolAddress((void**)&p_wo,   g_wo);
    cudaGetSymbolAddress((void**)&p_w1,   g_w1);
    cudaGetSymbolAddress((void**)&p_w2,   g_w2);

    cudaFuncSetAttribute(gemm_mma<false, false, false>,
                         cudaFuncAttributeMaxDynamicSharedMemorySize, GEMM_SMEM);
    cudaFuncSetAttribute(gemm_mma<false, true, false>,
                         cudaFuncAttributeMaxDynamicSharedMemorySize, GEMM_SMEM);
    cudaFuncSetAttribute(gemm_mma<true, true, true>,
                         cudaFuncAttributeMaxDynamicSharedMemorySize, GEMM_SMEM);
    cudaFuncSetAttribute(attn_mma_kernel,
                         cudaFuncAttributeMaxDynamicSharedMemorySize, ATTN_SMEM);

    const int RB = 1024;

    // pre-round + permute weights and x; concat QKV biases
    round_perm_kernel<<<RB, 256>>>(WQ, p_wqkv,                       DD, (size_t)DD * DD / 4);
    round_perm_kernel<<<RB, 256>>>(WK, p_wqkv + (size_t)DD * DD,     DD, (size_t)DD * DD / 4);
    round_perm_kernel<<<RB, 256>>>(WV, p_wqkv + (size_t)2 * DD * DD, DD, (size_t)DD * DD / 4);
    round_perm_kernel<<<RB, 256>>>(WO, p_wo, DD,  (size_t)DD * DD / 4);
    round_perm_kernel<<<RB, 256>>>(W1, p_w1, DD,  (size_t)FFN * DD / 4);
    round_perm_kernel<<<RB, 256>>>(W2, p_w2, FFN, (size_t)DD * FFN / 4);
    round_perm_kernel<<<RB, 256>>>(x,  p_xr, DD,  (size_t)MM * DD / 4);
    cudaMemcpyAsync(p_bqkv,          bQ, DD * sizeof(float), cudaMemcpyDeviceToDevice);
    cudaMemcpyAsync(p_bqkv + DD,     bK, DD * sizeof(float), cudaMemcpyDeviceToDevice);
    cudaMemcpyAsync(p_bqkv + 2 * DD, bV, DD * sizeof(float), cudaMemcpyDeviceToDevice);

    const dim3 gQKV(QKVS / 128, MM / 128);   // (24, 64)
    const dim3 gD(DD / 128, MM / 128);       // (8, 64)
    const dim3 gF(FFN / 128, MM / 128);      // (32, 64)

    // fused QKV projection (output rounded, NORMAL layout for attention)
    gemm_mma<false, true, false><<<gQKV, 128, GEMM_SMEM>>>(p_xr, p_wqkv, p_bqkv, p_qkv, MM, QKVS, DD);

    // causal attention (rounded+permuted output)
    attn_mma_kernel<<<dim3(TT / 64, HH, BB), 128, ATTN_SMEM>>>(p_qkv, p_attn);

    // output projection + LN1 (LN1 writes fp32 residual + rounded permuted copy)
    gemm_mma<false, false, false><<<gD, 128, GEMM_SMEM>>>(p_attn, p_wo, bO, p_proj, MM, DD, DD);
    add_ln_kernel<true><<<MM, 256>>>(x, p_proj, g1, be1, p_x1, p_x1r);

    // FFN + LN2 (ffn1 rounded+permuted for W2 GEMM)
    gemm_mma<true, true, true><<<gF, 128, GEMM_SMEM>>>(p_x1r, p_w1, b1, p_ffn1, MM, FFN, DD);
    gemm_mma<false, false, false><<<gD, 128, GEMM_SMEM>>>(p_ffn1, p_w2, b2, p_ffn2, MM, DD, FFN);
    add_ln_kernel<false><<<MM, 256>>>(p_x1, p_ffn2, g2, be2, out, nullptr);
}

// round 16
// speedup vs baseline: 8.1573x; 1.8145x over previous
#include <cuda_runtime.h>
#include <cuda_fp16.h>
#include <math_constants.h>
#include <cstdint>

// Problem constants
#define BB 4
#define TT 2048
#define DD 1024
#define HH 16
#define DKK 64
#define FFN 4096
#define MM (BB * TT)      // 8192 rows
#define QKVS (3 * DD)     // fused QKV row stride

// ---------------- scratch (device globals; no runtime allocation) ------------
__device__ __half g_xh[MM * DD];                // x in fp16
__device__ __half g_qkvh[(size_t)MM * QKVS];    // fused QKV out (fp16)
__device__ __half g_attnh[MM * DD];             // attn out (fp16)
__device__ float  g_proj[MM * DD];              // WO out (fp32, pre-LN)
__device__ float  g_x1[MM * DD];                // LN1 out fp32 (residual)
__device__ __half g_x1h[MM * DD];               // LN1 out fp16 (GEMM A)
__device__ __half g_ffn1h[(size_t)MM * FFN];    // relu out (fp16)
__device__ float  g_ffn2[MM * DD];              // W2 out (fp32, pre-LN)
// fp16 weights
__device__ __half g_wqkvh[(size_t)QKVS * DD];
__device__ float  g_bqkv[QKVS];
__device__ __half g_woh[DD * DD];
__device__ __half g_w1h[(size_t)FFN * DD];
__device__ __half g_w2h[(size_t)DD * FFN];

// ---------------- helpers -----------------------------------------------------
__device__ __forceinline__ void cp_async16(uint32_t smem_addr, const void* gptr) {
    asm volatile("cp.async.ca.shared.global [%0], [%1], 16;\n"
                 :: "r"(smem_addr), "l"(gptr));
}
__device__ __forceinline__ void cp_commit() {
    asm volatile("cp.async.commit_group;\n" ::: "memory");
}
template<int N>
__device__ __forceinline__ void cp_wait_group() {
    asm volatile("cp.async.wait_group %0;\n" :: "n"(N) : "memory");
}
__device__ __forceinline__ void cp_wait0() { cp_wait_group<0>(); }

__device__ __forceinline__ void ldsm_x4(uint32_t& r0, uint32_t& r1, uint32_t& r2,
                                        uint32_t& r3, uint32_t addr) {
    asm volatile("ldmatrix.sync.aligned.m8n8.x4.shared.b16 {%0,%1,%2,%3}, [%4];"
                 : "=r"(r0), "=r"(r1), "=r"(r2), "=r"(r3) : "r"(addr));
}
__device__ __forceinline__ void ldsm_x4_t(uint32_t& r0, uint32_t& r1, uint32_t& r2,
                                          uint32_t& r3, uint32_t addr) {
    asm volatile("ldmatrix.sync.aligned.m8n8.x4.trans.shared.b16 {%0,%1,%2,%3}, [%4];"
                 : "=r"(r0), "=r"(r1), "=r"(r2), "=r"(r3) : "r"(addr));
}

// mma m16n8k16 fp16 in, fp32 accum
__device__ __forceinline__ void mma_f16(float c[4], uint32_t a0, uint32_t a1,
                                        uint32_t a2, uint32_t a3,
                                        uint32_t b0, uint32_t b1) {
    asm volatile(
        "mma.sync.aligned.m16n8k16.row.col.f32.f16.f16.f32 "
        "{%0,%1,%2,%3}, {%4,%5,%6,%7}, {%8,%9}, {%0,%1,%2,%3};\n"
        : "+f"(c[0]), "+f"(c[1]), "+f"(c[2]), "+f"(c[3])
        : "r"(a0), "r"(a1), "r"(a2), "r"(a3), "r"(b0), "r"(b1));
}

__device__ __forceinline__ uint32_t packh2(float a, float b) {
    __half2 h = __floats2half2_rn(a, b);
    return *reinterpret_cast<uint32_t*>(&h);
}

// ---------------- fp32 -> fp16 convert ----------------------------------------
__global__ __launch_bounds__(256) void cvt_h_kernel(
    const float* __restrict__ src, __half* __restrict__ dst, size_t n4)
{
    const size_t i = (size_t)blockIdx.x * blockDim.x + threadIdx.x;
    const size_t stride = (size_t)gridDim.x * blockDim.x;
    for (size_t j = i; j < n4; j += stride) {
        float4 v = ((const float4*)src)[j];
        uint2 o;
        o.x = packh2(v.x, v.y);
        o.y = packh2(v.z, v.w);
        ((uint2*)dst)[j] = o;
    }
}

// ---------------- fp16 mma GEMM: C[M,N] = A[M,K] @ W[N,K]^T + bias ------------
// CTA 128x128, K-chunk 64 halves (128B rows, SW128 xor swizzle), 3-stage
// cp.async. 8 warps: 2(M) x 4(N), warp tile 64x32. ldmatrix operand loads.
constexpr int GSTAGE_B = 2 * 128 * 128;           // A+B bytes per stage (32KB)
constexpr int GEMM_SMEM = 3 * GSTAGE_B;           // 98304

template <bool RELU, bool OUTH>
__global__ __launch_bounds__(256, 2) void gemm_h(
    const __half* __restrict__ A, const __half* __restrict__ W,
    const float* __restrict__ bias, float* __restrict__ Cf, __half* __restrict__ Ch,
    int M, int N, int K)
{
    extern __shared__ __align__(128) char smem[];
    const uint32_t sbase = (uint32_t)__cvta_generic_to_shared(smem);

    const int tid  = threadIdx.x;
    const int lane = tid & 31;
    const int wid  = tid >> 5;
    const int wm = wid & 1;           // 0..1  (M)
    const int wn = wid >> 1;          // 0..3  (N)
    const int g  = lane >> 2;
    const int t4 = lane & 3;
    const int row0 = blockIdx.y * 128;
    const int col0 = blockIdx.x * 128;

    const int lane15 = lane & 15;
    const int khi    = (lane & 16) ? 16 : 0;   // +8 halves = +16B

    // loader: per matrix 128 rows x 8 x 16B chunks = 1024 chunks; 4/thread
    auto load_chunk = [&](int s, int c) {
        const uint32_t ab = sbase + (uint32_t)s * GSTAGE_B;
        const uint32_t bb = ab + 128 * 128;
        const size_t kofs = (size_t)c * 64;
        const __half* gA = A + (size_t)row0 * K + kofs;
        const __half* gW = W + (size_t)col0 * K + kofs;
        #pragma unroll
        for (int i = 0; i < 4; i++) {
            int e = i * 256 + tid;
            int r = e >> 3;
            int c16 = e & 7;
            uint32_t so = (uint32_t)r * 128 + (((uint32_t)c16 * 16) ^ (((uint32_t)r & 7) * 16));
            cp_async16(ab + so, gA + (size_t)r * K + c16 * 8);
            cp_async16(bb + so, gW + (size_t)r * K + c16 * 8);
        }
        cp_commit();
    };

    float acc[4][4][4];
    #pragma unroll
    for (int mi = 0; mi < 4; mi++)
        #pragma unroll
        for (int ni = 0; ni < 4; ni++)
            #pragma unroll
            for (int r = 0; r < 4; r++) acc[mi][ni][r] = 0.0f;

    const int nc = K / 64;
    load_chunk(0, 0);
    if (nc > 1) load_chunk(1, 1);

    for (int c = 0; c < nc; c++) {
        if (c + 1 < nc) cp_wait_group<1>(); else cp_wait_group<0>();
        __syncthreads();
        if (c + 2 < nc) load_chunk((c + 2) % 3, c + 2);

        const uint32_t aS = sbase + (uint32_t)(c % 3) * GSTAGE_B;
        const uint32_t bS = aS + 128 * 128;

        #pragma unroll
        for (int ks = 0; ks < 4; ks++) {
            const uint32_t kb = (uint32_t)(ks * 32 + khi);
            uint32_t a[4][4];
            #pragma unroll
            for (int mi = 0; mi < 4; mi++) {
                const uint32_t r = (uint32_t)(wm * 64 + mi * 16 + lane15);
                ldsm_x4(a[mi][0], a[mi][1], a[mi][2], a[mi][3],
                        aS + r * 128 + (kb ^ ((r & 7) * 16)));
            }
            uint32_t b[4][2];
            #pragma unroll
            for (int nb4 = 0; nb4 < 2; nb4++) {
                const uint32_t r = (uint32_t)(wn * 32 + nb4 * 16 + lane15);
                uint32_t t0, t1, t2, t3;
                ldsm_x4(t0, t1, t2, t3, bS + r * 128 + (kb ^ ((r & 7) * 16)));
                b[nb4 * 2 + 0][0] = t0; b[nb4 * 2 + 0][1] = t2;
                b[nb4 * 2 + 1][0] = t1; b[nb4 * 2 + 1][1] = t3;
            }
            #pragma unroll
            for (int mi = 0; mi < 4; mi++)
                #pragma unroll
                for (int ni = 0; ni < 4; ni++)
                    mma_f16(acc[mi][ni], a[mi][0], a[mi][1], a[mi][2], a[mi][3],
                            b[ni][0], b[ni][1]);
        }
        __syncthreads();
    }

    // ---- epilogue ----
    #pragma unroll
    for (int ni = 0; ni < 4; ni++) {
        const int gcol = col0 + wn * 32 + ni * 8 + 2 * t4;
        const float b0 = bias[gcol], b1 = bias[gcol + 1];
        #pragma unroll
        for (int mi = 0; mi < 4; mi++) {
            const int row = row0 + wm * 64 + mi * 16 + g;
            float v0 = acc[mi][ni][0] + b0;
            float v1 = acc[mi][ni][1] + b1;
            float v2 = acc[mi][ni][2] + b0;
            float v3 = acc[mi][ni][3] + b1;
            if (RELU) {
                v0 = fmaxf(v0, 0.0f); v1 = fmaxf(v1, 0.0f);
                v2 = fmaxf(v2, 0.0f); v3 = fmaxf(v3, 0.0f);
            }
            if (OUTH) {
                *(uint32_t*)(Ch + (size_t)row * N + gcol)       = packh2(v0, v1);
                *(uint32_t*)(Ch + (size_t)(row + 8) * N + gcol) = packh2(v2, v3);
            } else {
                *(float2*)(Cf + (size_t)row * N + gcol)       = make_float2(v0, v1);
                *(float2*)(Cf + (size_t)(row + 8) * N + gcol) = make_float2(v2, v3);
            }
        }
    }
}

// ---------------- fp16 flash attention (causal) --------------------------------
// 128 threads = 4 warps, 64 q-rows/block (16 per warp). K/V 64-key tiles,
// double-buffered cp.async. Q/K via ldmatrix, V via ldmatrix.trans; P stays
// in registers (S c-frag -> PV a-frag repack).
constexpr int AQ_B  = 0;                 // Q  [64][64] halves, 8KB
constexpr int AK_B  = 8192;              // K  [2][64][64]
constexpr int AV_B  = 8192 + 16384;      // V  [2][64][64]
constexpr int ATTN_SMEM = AV_B + 16384;  // 40960 B

__global__ __launch_bounds__(128, 3) void attn_h_kernel(
    const __half* __restrict__ QKV, __half* __restrict__ O)
{
    extern __shared__ __align__(128) char sm[];
    const uint32_t sbase = (uint32_t)__cvta_generic_to_shared(sm);

    const int tid  = threadIdx.x;
    const int lane = tid & 31;
    const int warp = tid >> 5;
    const int g    = lane >> 2;
    const int t4   = lane & 3;
    const int qt = blockIdx.x;
    const int h  = blockIdx.y;
    const int b  = blockIdx.z;

    const int lane15 = lane & 15;
    const int khi    = (lane & 16) ? 16 : 0;

    // ---- Q tile + KV tile 0 loads (one commit group)
    {
        const __half* Qp = QKV + ((size_t)(b * TT + qt * 64)) * QKVS + h * 64;
        #pragma unroll
        for (int i = 0; i < 4; i++) {
            int e = i * 128 + tid;
            int r = e >> 3;
            int c16 = e & 7;
            uint32_t so = (uint32_t)r * 128 + (((uint32_t)c16 * 16) ^ (((uint32_t)r & 7) * 16));
            cp_async16(sbase + AQ_B + so, Qp + (size_t)r * QKVS + c16 * 8);
        }
    }
    auto load_kv = [&](int buf, int kt) {
        const __half* Kp = QKV + ((size_t)(b * TT + kt * 64)) * QKVS + DD + h * 64;
        const __half* Vp = Kp + DD;
        const uint32_t kb = sbase + AK_B + buf * 8192;
        const uint32_t vb = sbase + AV_B + buf * 8192;
        #pragma unroll
        for (int i = 0; i < 4; i++) {
            int e = i * 128 + tid;
            int r = e >> 3;
            int c16 = e & 7;
            uint32_t so = (uint32_t)r * 128 + (((uint32_t)c16 * 16) ^ (((uint32_t)r & 7) * 16));
            cp_async16(kb + so, Kp + (size_t)r * QKVS + c16 * 8);
            cp_async16(vb + so, Vp + (size_t)r * QKVS + c16 * 8);
        }
        cp_commit();
    };
    load_kv(0, 0);

    float m0 = -1e30f, m1 = -1e30f, l0 = 0.0f, l1 = 0.0f;
    float co[8][4];
    #pragma unroll
    for (int ni = 0; ni < 8; ni++)
        #pragma unroll
        for (int r = 0; r < 4; r++) co[ni][r] = 0.0f;

    const int row0g = qt * 64 + warp * 16 + g;

    for (int kt = 0; kt <= qt; kt++) {
        const int buf = kt & 1;
        const uint32_t kS = sbase + AK_B + buf * 8192;
        const uint32_t vS = sbase + AV_B + buf * 8192;

        cp_wait0();
        __syncthreads();
        if (kt < qt) load_kv(buf ^ 1, kt + 1);

        // ---- S = Q @ K^T : 16 q x 64 keys per warp, 4 k16 steps over dk=64
        float cs[8][4];
        #pragma unroll
        for (int ni = 0; ni < 8; ni++)
            #pragma unroll
            for (int r = 0; r < 4; r++) cs[ni][r] = 0.0f;

        #pragma unroll
        for (int ks = 0; ks < 4; ks++) {
            const uint32_t kb = (uint32_t)(ks * 32 + khi);
            uint32_t a0, a1, a2, a3;
            {
                const uint32_t r = (uint32_t)(warp * 16 + lane15);
                ldsm_x4(a0, a1, a2, a3, sbase + AQ_B + r * 128 + (kb ^ ((r & 7) * 16)));
            }
            #pragma unroll
            for (int nb4 = 0; nb4 < 4; nb4++) {
                const uint32_t r = (uint32_t)(nb4 * 16 + lane15);
                uint32_t t0, t1, t2, t3;
                ldsm_x4(t0, t1, t2, t3, kS + r * 128 + (kb ^ ((r & 7) * 16)));
                mma_f16(cs[nb4 * 2 + 0], a0, a1, a2, a3, t0, t2);
                mma_f16(cs[nb4 * 2 + 1], a0, a1, a2, a3, t1, t3);
            }
        }

        // ---- scale + causal mask (diagonal tile only)
        const float SC = 0.125f;
        float rm0 = -1e30f, rm1 = -1e30f;
        #pragma unroll
        for (int ni = 0; ni < 8; ni++) {
            float s0 = cs[ni][0] * SC, s1 = cs[ni][1] * SC;
            float s2 = cs[ni][2] * SC, s3 = cs[ni][3] * SC;
            if (kt == qt) {
                const int colb = kt * 64 + ni * 8 + 2 * t4;
                if (colb     > row0g)     s0 = -1e30f;
                if (colb + 1 > row0g)     s1 = -1e30f;
                if (colb     > row0g + 8) s2 = -1e30f;
                if (colb + 1 > row0g + 8) s3 = -1e30f;
            }
            cs[ni][0] = s0; cs[ni][1] = s1; cs[ni][2] = s2; cs[ni][3] = s3;
            rm0 = fmaxf(rm0, fmaxf(s0, s1));
            rm1 = fmaxf(rm1, fmaxf(s2, s3));
        }
        rm0 = fmaxf(rm0, __shfl_xor_sync(0xffffffffu, rm0, 1));
        rm0 = fmaxf(rm0, __shfl_xor_sync(0xffffffffu, rm0, 2));
        rm1 = fmaxf(rm1, __shfl_xor_sync(0xffffffffu, rm1, 1));
        rm1 = fmaxf(rm1, __shfl_xor_sync(0xffffffffu, rm1, 2));

        const float mt0 = fmaxf(m0, rm0), mt1 = fmaxf(m1, rm1);
        const float corr0 = __expf(m0 - mt0), corr1 = __expf(m1 - mt1);
        m0 = mt0; m1 = mt1;

        // ---- P = exp(S-m) rounded to fp16 (packed straight into PV a-frags)
        uint32_t pa[8][2];
        float sum0 = 0.0f, sum1 = 0.0f;
        #pragma unroll
        for (int ni = 0; ni < 8; ni++) {
            float p0 = __expf(cs[ni][0] - mt0);
            float p1 = __expf(cs[ni][1] - mt0);
            float p2 = __expf(cs[ni][2] - mt1);
            float p3 = __expf(cs[ni][3] - mt1);
            __half2 h0 = __floats2half2_rn(p0, p1);
            __half2 h1 = __floats2half2_rn(p2, p3);
            pa[ni][0] = *reinterpret_cast<uint32_t*>(&h0);
            pa[ni][1] = *reinterpret_cast<uint32_t*>(&h1);
            float2 f0 = __half22float2(h0);
            float2 f1 = __half22float2(h1);
            sum0 += f0.x + f0.y;
            sum1 += f1.x + f1.y;
        }
        sum0 += __shfl_xor_sync(0xffffffffu, sum0, 1);
        sum0 += __shfl_xor_sync(0xffffffffu, sum0, 2);
        sum1 += __shfl_xor_sync(0xffffffffu, sum1, 1);
        sum1 += __shfl_xor_sync(0xffffffffu, sum1, 2);
        l0 = l0 * corr0 + sum0;
        l1 = l1 * corr1 + sum1;

        #pragma unroll
        for (int ni = 0; ni < 8; ni++) {
            co[ni][0] *= corr0; co[ni][1] *= corr0;
            co[ni][2] *= corr1; co[ni][3] *= corr1;
        }

        // ---- O += P @ V : 4 k16 steps over 64 keys; V via ldmatrix.trans
        #pragma unroll
        for (int ki = 0; ki < 4; ki++) {
            const uint32_t a0 = pa[2 * ki][0],     a1 = pa[2 * ki][1];
            const uint32_t a2 = pa[2 * ki + 1][0], a3 = pa[2 * ki + 1][1];
            #pragma unroll
            for (int db = 0; db < 4; db++) {
                const uint32_t r = (uint32_t)(16 * ki + lane15);
                const uint32_t cb = (uint32_t)(db * 32 + khi);
                uint32_t t0, t1, t2, t3;
                ldsm_x4_t(t0, t1, t2, t3, vS + r * 128 + (cb ^ ((r & 7) * 16)));
                mma_f16(co[db * 2 + 0], a0, a1, a2, a3, t0, t1);
                mma_f16(co[db * 2 + 1], a0, a1, a2, a3, t2, t3);
            }
        }
    }

    // ---- normalize + fp16 store
    const float inv0 = 1.0f / l0, inv1 = 1.0f / l1;
    const size_t gr0 = (size_t)(b * TT) + qt * 64 + warp * 16 + g;
    __half* Or0 = O + gr0 * DD + h * 64;
    __half* Or1 = Or0 + (size_t)8 * DD;
    #pragma unroll
    for (int ni = 0; ni < 8; ni++) {
        const int cc = ni * 8 + 2 * t4;
        *(uint32_t*)(Or0 + cc) = packh2(co[ni][0] * inv0, co[ni][1] * inv0);
        *(uint32_t*)(Or1 + cc) = packh2(co[ni][2] * inv1, co[ni][3] * inv1);
    }
}

// ---------------- fused residual-add + LayerNorm ------------------------------
// WRITE_H: also writes fp16 copy (next GEMM's A operand).
template <bool WRITE_H>
__global__ __launch_bounds__(256) void add_ln_kernel(
    const float* __restrict__ A, const float* __restrict__ Bv,
    const float* __restrict__ g, const float* __restrict__ be,
    float* __restrict__ out, __half* __restrict__ out_h)
{
    const int row = blockIdx.x;
    const int tid = threadIdx.x;
    const size_t base = (size_t)row * DD + tid * 4;

    float4 av = *(const float4*)(A + base);
    float4 bv = *(const float4*)(Bv + base);
    float y0 = av.x + bv.x, y1 = av.y + bv.y, y2 = av.z + bv.z, y3 = av.w + bv.w;

    float s  = y0 + y1 + y2 + y3;
    float ss = y0 * y0 + y1 * y1 + y2 * y2 + y3 * y3;

    #pragma unroll
    for (int o = 16; o > 0; o >>= 1) {
        s  += __shfl_xor_sync(0xffffffffu, s, o);
        ss += __shfl_xor_sync(0xffffffffu, ss, o);
    }
    __shared__ float red_s[8], red_ss[8];
    const int wid = tid >> 5;
    if ((tid & 31) == 0) { red_s[wid] = s; red_ss[wid] = ss; }
    __syncthreads();
    float ts = 0.0f, tss = 0.0f;
    #pragma unroll
    for (int w = 0; w < 8; w++) { ts += red_s[w]; tss += red_ss[w]; }

    const float mu   = ts * (1.0f / DD);
    const float var  = tss * (1.0f / DD) - mu * mu;
    const float rstd = rsqrtf(var + 1e-5f);

    float4 gv  = *(const float4*)(g  + tid * 4);
    float4 bev = *(const float4*)(be + tid * 4);
    float4 ov;
    ov.x = (y0 - mu) * rstd * gv.x + bev.x;
    ov.y = (y1 - mu) * rstd * gv.y + bev.y;
    ov.z = (y2 - mu) * rstd * gv.z + bev.z;
    ov.w = (y3 - mu) * rstd * gv.w + bev.w;
    *(float4*)(out + base) = ov;
    if (WRITE_H) {
        uint2 o;
        o.x = packh2(ov.x, ov.y);
        o.y = packh2(ov.z, ov.w);
        *(uint2*)(out_h + base) = o;
    }
}

// ---------------- launch ------------------------------------------------------
extern "C" void kernel_launch(void* const* d_in, const int* in_sizes, int n_in,
                              void* d_out, int out_size)
{
    const float* x   = (const float*)d_in[0];
    const float* WQ  = (const float*)d_in[1];
    const float* bQ  = (const float*)d_in[2];
    const float* WK  = (const float*)d_in[3];
    const float* bK  = (const float*)d_in[4];
    const float* WV  = (const float*)d_in[5];
    const float* bV  = (const float*)d_in[6];
    const float* WO  = (const float*)d_in[7];
    const float* bO  = (const float*)d_in[8];
    const float* W1  = (const float*)d_in[9];
    const float* b1  = (const float*)d_in[10];
    const float* W2  = (const float*)d_in[11];
    const float* b2  = (const float*)d_in[12];
    const float* g1  = (const float*)d_in[13];
    const float* be1 = (const float*)d_in[14];
    const float* g2  = (const float*)d_in[15];
    const float* be2 = (const float*)d_in[16];
    float* out = (float*)d_out;

    __half *p_xh, *p_qkvh, *p_attnh, *p_x1h, *p_ffn1h;
    __half *p_wqkvh, *p_woh, *p_w1h, *p_w2h;
    float *p_proj, *p_x1, *p_ffn2, *p_bqkv;
    cudaGetSymbolAddress((void**)&p_xh,    g_xh);
    cudaGetSymbolAddress((void**)&p_qkvh,  g_qkvh);
    cudaGetSymbolAddress((void**)&p_attnh, g_attnh);
    cudaGetSymbolAddress((void**)&p_proj,  g_proj);
    cudaGetSymbolAddress((void**)&p_x1,    g_x1);
    cudaGetSymbolAddress((void**)&p_x1h,   g_x1h);
    cudaGetSymbolAddress((void**)&p_ffn1h, g_ffn1h);
    cudaGetSymbolAddress((void**)&p_ffn2,  g_ffn2);
    cudaGetSymbolAddress((void**)&p_wqkvh, g_wqkvh);
    cudaGetSymbolAddress((void**)&p_bqkv,  g_bqkv);
    cudaGetSymbolAddress((void**)&p_woh,   g_woh);
    cudaGetSymbolAddress((void**)&p_w1h,   g_w1h);
    cudaGetSymbolAddress((void**)&p_w2h,   g_w2h);

    cudaFuncSetAttribute(gemm_h<false, true>,
                         cudaFuncAttributeMaxDynamicSharedMemorySize, GEMM_SMEM);
    cudaFuncSetAttribute(gemm_h<false, false>,
                         cudaFuncAttributeMaxDynamicSharedMemorySize, GEMM_SMEM);
    cudaFuncSetAttribute(gemm_h<true, true>,
                         cudaFuncAttributeMaxDynamicSharedMemorySize, GEMM_SMEM);
    cudaFuncSetAttribute(attn_h_kernel,
                         cudaFuncAttributeMaxDynamicSharedMemorySize, ATTN_SMEM);

    const int RB = 1024;

    // fp32 -> fp16 weights + x; concat QKV biases (fp32)
    cvt_h_kernel<<<RB, 256>>>(WQ, p_wqkvh,                       (size_t)DD * DD / 4);
    cvt_h_kernel<<<RB, 256>>>(WK, p_wqkvh + (size_t)DD * DD,     (size_t)DD * DD / 4);
    cvt_h_kernel<<<RB, 256>>>(WV, p_wqkvh + (size_t)2 * DD * DD, (size_t)DD * DD / 4);
    cvt_h_kernel<<<RB, 256>>>(WO, p_woh, (size_t)DD * DD / 4);
    cvt_h_kernel<<<RB, 256>>>(W1, p_w1h, (size_t)FFN * DD / 4);
    cvt_h_kernel<<<RB, 256>>>(W2, p_w2h, (size_t)DD * FFN / 4);
    cvt_h_kernel<<<RB, 256>>>(x,  p_xh,  (size_t)MM * DD / 4);
    cudaMemcpyAsync(p_bqkv,          bQ, DD * sizeof(float), cudaMemcpyDeviceToDevice);
    cudaMemcpyAsync(p_bqkv + DD,     bK, DD * sizeof(float), cudaMemcpyDeviceToDevice);
    cudaMemcpyAsync(p_bqkv + 2 * DD, bV, DD * sizeof(float), cudaMemcpyDeviceToDevice);

    const dim3 gQKV(QKVS / 128, MM / 128);   // (24, 64)
    const dim3 gD(DD / 128, MM / 128);       // (8, 64)
    const dim3 gF(FFN / 128, MM / 128);      // (32, 64)

    // fused QKV projection (fp16 out)
    gemm_h<false, true><<<gQKV, 256, GEMM_SMEM>>>(p_xh, p_wqkvh, p_bqkv,
                                                  nullptr, p_qkvh, MM, QKVS, DD);

    // causal attention (fp16)
    attn_h_kernel<<<dim3(TT / 64, HH, BB), 128, ATTN_SMEM>>>(p_qkvh, p_attnh);

    // output projection (fp32 out) + LN1 (fp32 residual + fp16 copy)
    gemm_h<false, false><<<gD, 256, GEMM_SMEM>>>(p_attnh, p_woh, bO,
                                                 p_proj, nullptr, MM, DD, DD);
    add_ln_kernel<true><<<MM, 256>>>(x, p_proj, g1, be1, p_x1, p_x1h);

    // FFN + LN2
    gemm_h<true, true><<<gF, 256, GEMM_SMEM>>>(p_x1h, p_w1h, b1,
                                               nullptr, p_ffn1h, MM, FFN, DD);
    gemm_h<false, false><<<gD, 256, GEMM_SMEM>>>(p_ffn1h, p_w2h, b2,
                                                 p_ffn2, nullptr, MM, DD, FFN);
    add_ln_kernel<false><<<MM, 256>>>(p_x1, p_ffn2, g2, be2, out, nullptr);
}

// round 17
// speedup vs baseline: 8.2678x; 1.0135x over previous
#include <cuda_runtime.h>
#include <cuda_fp16.h>
#include <math_constants.h>
#include <cstdint>

// Problem constants
#define BB 4
#define TT 2048
#define DD 1024
#define HH 16
#define DKK 64
#define FFN 4096
#define MM (BB * TT)      // 8192 rows
#define QKVS (3 * DD)     // fused QKV row stride

// ---------------- scratch (device globals; no runtime allocation) ------------
__device__ __half g_xh[MM * DD];                // x in fp16
__device__ __half g_qkvh[(size_t)MM * QKVS];    // fused QKV out (fp16)
__device__ __half g_attnh[MM * DD];             // attn out (fp16)
__device__ float  g_proj[MM * DD];              // WO out (fp32, pre-LN)
__device__ float  g_x1[MM * DD];                // LN1 out fp32 (residual)
__device__ __half g_x1h[MM * DD];               // LN1 out fp16 (GEMM A)
__device__ __half g_ffn1h[(size_t)MM * FFN];    // relu out (fp16)
__device__ float  g_ffn2[MM * DD];              // W2 out (fp32, pre-LN)
// fp16 weights
__device__ __half g_wqkvh[(size_t)QKVS * DD];
__device__ float  g_bqkv[QKVS];
__device__ __half g_woh[DD * DD];
__device__ __half g_w1h[(size_t)FFN * DD];
__device__ __half g_w2h[(size_t)DD * FFN];

// ---------------- helpers -----------------------------------------------------
__device__ __forceinline__ void cp_async16(uint32_t smem_addr, const void* gptr) {
    asm volatile("cp.async.ca.shared.global [%0], [%1], 16;\n"
                 :: "r"(smem_addr), "l"(gptr));
}
__device__ __forceinline__ void cp_commit() {
    asm volatile("cp.async.commit_group;\n" ::: "memory");
}
template<int N>
__device__ __forceinline__ void cp_wait_group() {
    asm volatile("cp.async.wait_group %0;\n" :: "n"(N) : "memory");
}
__device__ __forceinline__ void cp_wait0() { cp_wait_group<0>(); }

__device__ __forceinline__ void ldsm_x4(uint32_t& r0, uint32_t& r1, uint32_t& r2,
                                        uint32_t& r3, uint32_t addr) {
    asm volatile("ldmatrix.sync.aligned.m8n8.x4.shared.b16 {%0,%1,%2,%3}, [%4];"
                 : "=r"(r0), "=r"(r1), "=r"(r2), "=r"(r3) : "r"(addr));
}
__device__ __forceinline__ void ldsm_x4_t(uint32_t& r0, uint32_t& r1, uint32_t& r2,
                                          uint32_t& r3, uint32_t addr) {
    asm volatile("ldmatrix.sync.aligned.m8n8.x4.trans.shared.b16 {%0,%1,%2,%3}, [%4];"
                 : "=r"(r0), "=r"(r1), "=r"(r2), "=r"(r3) : "r"(addr));
}

// mma m16n8k16 fp16 in, fp32 accum
__device__ __forceinline__ void mma_f16(float c[4], uint32_t a0, uint32_t a1,
                                        uint32_t a2, uint32_t a3,
                                        uint32_t b0, uint32_t b1) {
    asm volatile(
        "mma.sync.aligned.m16n8k16.row.col.f32.f16.f16.f32 "
        "{%0,%1,%2,%3}, {%4,%5,%6,%7}, {%8,%9}, {%0,%1,%2,%3};\n"
        : "+f"(c[0]), "+f"(c[1]), "+f"(c[2]), "+f"(c[3])
        : "r"(a0), "r"(a1), "r"(a2), "r"(a3), "r"(b0), "r"(b1));
}

__device__ __forceinline__ uint32_t packh2(float a, float b) {
    __half2 h = __floats2half2_rn(a, b);
    return *reinterpret_cast<uint32_t*>(&h);
}

// ---------------- single fused conversion kernel -------------------------------
// Converts all weights + x to fp16 and concatenates QKV biases, in ONE launch.
// Segment map in float4 units (each float4 -> 4 halves / 4 floats for biases).
constexpr size_t SEG_W  = (size_t)DD * DD / 4;       // 262144
constexpr size_t SEG_W1 = (size_t)FFN * DD / 4;      // 1048576
constexpr size_t SEG_X  = (size_t)MM * DD / 4;       // 2097152
constexpr size_t OFF_WQ = 0;
constexpr size_t OFF_WK = OFF_WQ + SEG_W;
constexpr size_t OFF_WV = OFF_WK + SEG_W;
constexpr size_t OFF_WO = OFF_WV + SEG_W;
constexpr size_t OFF_W1 = OFF_WO + SEG_W;
constexpr size_t OFF_W2 = OFF_W1 + SEG_W1;
constexpr size_t OFF_X  = OFF_W2 + SEG_W1;
constexpr size_t OFF_B  = OFF_X + SEG_X;             // biases: 3 x 256 float4
constexpr size_t CVT_TOTAL = OFF_B + 3 * (DD / 4);

__global__ __launch_bounds__(256) void cvt_all_kernel(
    const float* __restrict__ WQ, const float* __restrict__ WK,
    const float* __restrict__ WV, const float* __restrict__ WO,
    const float* __restrict__ W1, const float* __restrict__ W2,
    const float* __restrict__ x,
    const float* __restrict__ bQ, const float* __restrict__ bK,
    const float* __restrict__ bV)
{
    const size_t i = (size_t)blockIdx.x * blockDim.x + threadIdx.x;
    const size_t stride = (size_t)gridDim.x * blockDim.x;
    for (size_t j = i; j < CVT_TOTAL; j += stride) {
        const float* src;
        __half* dsth;
        size_t o;
        if (j < OFF_W1) {
            if (j < OFF_WK)      { src = WQ; o = j - OFF_WQ; dsth = g_wqkvh; }
            else if (j < OFF_WV) { src = WK; o = j - OFF_WK; dsth = g_wqkvh + (size_t)DD * DD; }
            else if (j < OFF_WO) { src = WV; o = j - OFF_WV; dsth = g_wqkvh + (size_t)2 * DD * DD; }
            else                 { src = WO; o = j - OFF_WO; dsth = g_woh; }
        } else if (j < OFF_W2) { src = W1; o = j - OFF_W1; dsth = g_w1h; }
        else if (j < OFF_X)    { src = W2; o = j - OFF_W2; dsth = g_w2h; }
        else if (j < OFF_B)    { src = x;  o = j - OFF_X;  dsth = g_xh; }
        else {
            // bias concat (fp32 copy, no conversion)
            size_t bj = j - OFF_B;
            const float* bs;
            float* bd;
            if (bj < DD / 4)          { bs = bQ; bd = g_bqkv;          }
            else if (bj < 2 * DD / 4) { bs = bK; bd = g_bqkv + DD;     bj -= DD / 4; }
            else                      { bs = bV; bd = g_bqkv + 2 * DD; bj -= 2 * (DD / 4); }
            ((float4*)bd)[bj] = ((const float4*)bs)[bj];
            continue;
        }
        float4 v = ((const float4*)src)[o];
        uint2 ov;
        ov.x = packh2(v.x, v.y);
        ov.y = packh2(v.z, v.w);
        ((uint2*)dsth)[o] = ov;
    }
}

// ---------------- fp16 mma GEMM: C[M,N] = A[M,K] @ W[N,K]^T + bias ------------
// CTA 128x128, K-chunk 64 halves (128B rows, SW128 xor swizzle), 3-stage
// cp.async. 8 warps: 2(M) x 4(N), warp tile 64x32. ldmatrix operand loads.
constexpr int GSTAGE_B = 2 * 128 * 128;           // A+B bytes per stage (32KB)
constexpr int GEMM_SMEM = 3 * GSTAGE_B;           // 98304

template <bool RELU, bool OUTH>
__global__ __launch_bounds__(256, 2) void gemm_h(
    const __half* __restrict__ A, const __half* __restrict__ W,
    const float* __restrict__ bias, float* __restrict__ Cf, __half* __restrict__ Ch,
    int M, int N, int K)
{
    extern __shared__ __align__(128) char smem[];
    const uint32_t sbase = (uint32_t)__cvta_generic_to_shared(smem);

    const int tid  = threadIdx.x;
    const int lane = tid & 31;
    const int wid  = tid >> 5;
    const int wm = wid & 1;           // 0..1  (M)
    const int wn = wid >> 1;          // 0..3  (N)
    const int g  = lane >> 2;
    const int t4 = lane & 3;
    const int row0 = blockIdx.y * 128;
    const int col0 = blockIdx.x * 128;

    const int lane15 = lane & 15;
    const int khi    = (lane & 16) ? 16 : 0;   // +8 halves = +16B

    // loader: per matrix 128 rows x 8 x 16B chunks = 1024 chunks; 4/thread
    auto load_chunk = [&](int s, int c) {
        const uint32_t ab = sbase + (uint32_t)s * GSTAGE_B;
        const uint32_t bb = ab + 128 * 128;
        const size_t kofs = (size_t)c * 64;
        const __half* gA = A + (size_t)row0 * K + kofs;
        const __half* gW = W + (size_t)col0 * K + kofs;
        #pragma unroll
        for (int i = 0; i < 4; i++) {
            int e = i * 256 + tid;
            int r = e >> 3;
            int c16 = e & 7;
            uint32_t so = (uint32_t)r * 128 + (((uint32_t)c16 * 16) ^ (((uint32_t)r & 7) * 16));
            cp_async16(ab + so, gA + (size_t)r * K + c16 * 8);
            cp_async16(bb + so, gW + (size_t)r * K + c16 * 8);
        }
        cp_commit();
    };

    float acc[4][4][4];
    #pragma unroll
    for (int mi = 0; mi < 4; mi++)
        #pragma unroll
        for (int ni = 0; ni < 4; ni++)
            #pragma unroll
            for (int r = 0; r < 4; r++) acc[mi][ni][r] = 0.0f;

    const int nc = K / 64;
    load_chunk(0, 0);
    if (nc > 1) load_chunk(1, 1);

    for (int c = 0; c < nc; c++) {
        if (c + 1 < nc) cp_wait_group<1>(); else cp_wait_group<0>();
        __syncthreads();
        if (c + 2 < nc) load_chunk((c + 2) % 3, c + 2);

        const uint32_t aS = sbase + (uint32_t)(c % 3) * GSTAGE_B;
        const uint32_t bS = aS + 128 * 128;

        #pragma unroll
        for (int ks = 0; ks < 4; ks++) {
            const uint32_t kb = (uint32_t)(ks * 32 + khi);
            uint32_t a[4][4];
            #pragma unroll
            for (int mi = 0; mi < 4; mi++) {
                const uint32_t r = (uint32_t)(wm * 64 + mi * 16 + lane15);
                ldsm_x4(a[mi][0], a[mi][1], a[mi][2], a[mi][3],
                        aS + r * 128 + (kb ^ ((r & 7) * 16)));
            }
            uint32_t b[4][2];
            #pragma unroll
            for (int nb4 = 0; nb4 < 2; nb4++) {
                const uint32_t r = (uint32_t)(wn * 32 + nb4 * 16 + lane15);
                uint32_t t0, t1, t2, t3;
                ldsm_x4(t0, t1, t2, t3, bS + r * 128 + (kb ^ ((r & 7) * 16)));
                b[nb4 * 2 + 0][0] = t0; b[nb4 * 2 + 0][1] = t2;
                b[nb4 * 2 + 1][0] = t1; b[nb4 * 2 + 1][1] = t3;
            }
            #pragma unroll
            for (int mi = 0; mi < 4; mi++)
                #pragma unroll
                for (int ni = 0; ni < 4; ni++)
                    mma_f16(acc[mi][ni], a[mi][0], a[mi][1], a[mi][2], a[mi][3],
                            b[ni][0], b[ni][1]);
        }
        __syncthreads();
    }

    // ---- epilogue ----
    #pragma unroll
    for (int ni = 0; ni < 4; ni++) {
        const int gcol = col0 + wn * 32 + ni * 8 + 2 * t4;
        const float b0 = bias[gcol], b1 = bias[gcol + 1];
        #pragma unroll
        for (int mi = 0; mi < 4; mi++) {
            const int row = row0 + wm * 64 + mi * 16 + g;
            float v0 = acc[mi][ni][0] + b0;
            float v1 = acc[mi][ni][1] + b1;
            float v2 = acc[mi][ni][2] + b0;
            float v3 = acc[mi][ni][3] + b1;
            if (RELU) {
                v0 = fmaxf(v0, 0.0f); v1 = fmaxf(v1, 0.0f);
                v2 = fmaxf(v2, 0.0f); v3 = fmaxf(v3, 0.0f);
            }
            if (OUTH) {
                *(uint32_t*)(Ch + (size_t)row * N + gcol)       = packh2(v0, v1);
                *(uint32_t*)(Ch + (size_t)(row + 8) * N + gcol) = packh2(v2, v3);
            } else {
                *(float2*)(Cf + (size_t)row * N + gcol)       = make_float2(v0, v1);
                *(float2*)(Cf + (size_t)(row + 8) * N + gcol) = make_float2(v2, v3);
            }
        }
    }
}

// ---------------- fp16 flash attention (causal) --------------------------------
// 128 threads = 4 warps, 64 q-rows/block (16 per warp). K/V 64-key tiles,
// double-buffered cp.async. Q/K via ldmatrix, V via ldmatrix.trans; P stays
// in registers (S c-frag -> PV a-frag repack).
constexpr int AQ_B  = 0;                 // Q  [64][64] halves, 8KB
constexpr int AK_B  = 8192;              // K  [2][64][64]
constexpr int AV_B  = 8192 + 16384;      // V  [2][64][64]
constexpr int ATTN_SMEM = AV_B + 16384;  // 40960 B

__global__ __launch_bounds__(128, 3) void attn_h_kernel(
    const __half* __restrict__ QKV, __half* __restrict__ O)
{
    extern __shared__ __align__(128) char sm[];
    const uint32_t sbase = (uint32_t)__cvta_generic_to_shared(sm);

    const int tid  = threadIdx.x;
    const int lane = tid & 31;
    const int warp = tid >> 5;
    const int g    = lane >> 2;
    const int t4   = lane & 3;
    const int qt = blockIdx.x;
    const int h  = blockIdx.y;
    const int b  = blockIdx.z;

    const int lane15 = lane & 15;
    const int khi    = (lane & 16) ? 16 : 0;

    // ---- Q tile + KV tile 0 loads (one commit group)
    {
        const __half* Qp = QKV + ((size_t)(b * TT + qt * 64)) * QKVS + h * 64;
        #pragma unroll
        for (int i = 0; i < 4; i++) {
            int e = i * 128 + tid;
            int r = e >> 3;
            int c16 = e & 7;
            uint32_t so = (uint32_t)r * 128 + (((uint32_t)c16 * 16) ^ (((uint32_t)r & 7) * 16));
            cp_async16(sbase + AQ_B + so, Qp + (size_t)r * QKVS + c16 * 8);
        }
    }
    auto load_kv = [&](int buf, int kt) {
        const __half* Kp = QKV + ((size_t)(b * TT + kt * 64)) * QKVS + DD + h * 64;
        const __half* Vp = Kp + DD;
        const uint32_t kb = sbase + AK_B + buf * 8192;
        const uint32_t vb = sbase + AV_B + buf * 8192;
        #pragma unroll
        for (int i = 0; i < 4; i++) {
            int e = i * 128 + tid;
            int r = e >> 3;
            int c16 = e & 7;
            uint32_t so = (uint32_t)r * 128 + (((uint32_t)c16 * 16) ^ (((uint32_t)r & 7) * 16));
            cp_async16(kb + so, Kp + (size_t)r * QKVS + c16 * 8);
            cp_async16(vb + so, Vp + (size_t)r * QKVS + c16 * 8);
        }
        cp_commit();
    };
    load_kv(0, 0);

    float m0 = -1e30f, m1 = -1e30f, l0 = 0.0f, l1 = 0.0f;
    float co[8][4];
    #pragma unroll
    for (int ni = 0; ni < 8; ni++)
        #pragma unroll
        for (int r = 0; r < 4; r++) co[ni][r] = 0.0f;

    const int row0g = qt * 64 + warp * 16 + g;

    for (int kt = 0; kt <= qt; kt++) {
        const int buf = kt & 1;
        const uint32_t kS = sbase + AK_B + buf * 8192;
        const uint32_t vS = sbase + AV_B + buf * 8192;

        cp_wait0();
        __syncthreads();
        if (kt < qt) load_kv(buf ^ 1, kt + 1);

        // ---- S = Q @ K^T : 16 q x 64 keys per warp, 4 k16 steps over dk=64
        float cs[8][4];
        #pragma unroll
        for (int ni = 0; ni < 8; ni++)
            #pragma unroll
            for (int r = 0; r < 4; r++) cs[ni][r] = 0.0f;

        #pragma unroll
        for (int ks = 0; ks < 4; ks++) {
            const uint32_t kb = (uint32_t)(ks * 32 + khi);
            uint32_t a0, a1, a2, a3;
            {
                const uint32_t r = (uint32_t)(warp * 16 + lane15);
                ldsm_x4(a0, a1, a2, a3, sbase + AQ_B + r * 128 + (kb ^ ((r & 7) * 16)));
            }
            #pragma unroll
            for (int nb4 = 0; nb4 < 4; nb4++) {
                const uint32_t r = (uint32_t)(nb4 * 16 + lane15);
                uint32_t t0, t1, t2, t3;
                ldsm_x4(t0, t1, t2, t3, kS + r * 128 + (kb ^ ((r & 7) * 16)));
                mma_f16(cs[nb4 * 2 + 0], a0, a1, a2, a3, t0, t2);
                mma_f16(cs[nb4 * 2 + 1], a0, a1, a2, a3, t1, t3);
            }
        }

        // ---- scale + causal mask (diagonal tile only)
        const float SC = 0.125f;
        float rm0 = -1e30f, rm1 = -1e30f;
        #pragma unroll
        for (int ni = 0; ni < 8; ni++) {
            float s0 = cs[ni][0] * SC, s1 = cs[ni][1] * SC;
            float s2 = cs[ni][2] * SC, s3 = cs[ni][3] * SC;
            if (kt == qt) {
                const int colb = kt * 64 + ni * 8 + 2 * t4;
                if (colb     > row0g)     s0 = -1e30f;
                if (colb + 1 > row0g)     s1 = -1e30f;
                if (colb     > row0g + 8) s2 = -1e30f;
                if (colb + 1 > row0g + 8) s3 = -1e30f;
            }
            cs[ni][0] = s0; cs[ni][1] = s1; cs[ni][2] = s2; cs[ni][3] = s3;
            rm0 = fmaxf(rm0, fmaxf(s0, s1));
            rm1 = fmaxf(rm1, fmaxf(s2, s3));
        }
        rm0 = fmaxf(rm0, __shfl_xor_sync(0xffffffffu, rm0, 1));
        rm0 = fmaxf(rm0, __shfl_xor_sync(0xffffffffu, rm0, 2));
        rm1 = fmaxf(rm1, __shfl_xor_sync(0xffffffffu, rm1, 1));
        rm1 = fmaxf(rm1, __shfl_xor_sync(0xffffffffu, rm1, 2));

        const float mt0 = fmaxf(m0, rm0), mt1 = fmaxf(m1, rm1);
        const float corr0 = __expf(m0 - mt0), corr1 = __expf(m1 - mt1);
        m0 = mt0; m1 = mt1;

        // ---- P = exp(S-m) rounded to fp16 (packed straight into PV a-frags)
        uint32_t pa[8][2];
        float sum0 = 0.0f, sum1 = 0.0f;
        #pragma unroll
        for (int ni = 0; ni < 8; ni++) {
            float p0 = __expf(cs[ni][0] - mt0);
            float p1 = __expf(cs[ni][1] - mt0);
            float p2 = __expf(cs[ni][2] - mt1);
            float p3 = __expf(cs[ni][3] - mt1);
            __half2 h0 = __floats2half2_rn(p0, p1);
            __half2 h1 = __floats2half2_rn(p2, p3);
            pa[ni][0] = *reinterpret_cast<uint32_t*>(&h0);
            pa[ni][1] = *reinterpret_cast<uint32_t*>(&h1);
            float2 f0 = __half22float2(h0);
            float2 f1 = __half22float2(h1);
            sum0 += f0.x + f0.y;
            sum1 += f1.x + f1.y;
        }
        sum0 += __shfl_xor_sync(0xffffffffu, sum0, 1);
        sum0 += __shfl_xor_sync(0xffffffffu, sum0, 2);
        sum1 += __shfl_xor_sync(0xffffffffu, sum1, 1);
        sum1 += __shfl_xor_sync(0xffffffffu, sum1, 2);
        l0 = l0 * corr0 + sum0;
        l1 = l1 * corr1 + sum1;

        #pragma unroll
        for (int ni = 0; ni < 8; ni++) {
            co[ni][0] *= corr0; co[ni][1] *= corr0;
            co[ni][2] *= corr1; co[ni][3] *= corr1;
        }

        // ---- O += P @ V : 4 k16 steps over 64 keys; V via ldmatrix.trans
        #pragma unroll
        for (int ki = 0; ki < 4; ki++) {
            const uint32_t a0 = pa[2 * ki][0],     a1 = pa[2 * ki][1];
            const uint32_t a2 = pa[2 * ki + 1][0], a3 = pa[2 * ki + 1][1];
            #pragma unroll
            for (int db = 0; db < 4; db++) {
                const uint32_t r = (uint32_t)(16 * ki + lane15);
                const uint32_t cb = (uint32_t)(db * 32 + khi);
                uint32_t t0, t1, t2, t3;
                ldsm_x4_t(t0, t1, t2, t3, vS + r * 128 + (cb ^ ((r & 7) * 16)));
                mma_f16(co[db * 2 + 0], a0, a1, a2, a3, t0, t1);
                mma_f16(co[db * 2 + 1], a0, a1, a2, a3, t2, t3);
            }
        }
    }

    // ---- normalize + fp16 store
    const float inv0 = 1.0f / l0, inv1 = 1.0f / l1;
    const size_t gr0 = (size_t)(b * TT) + qt * 64 + warp * 16 + g;
    __half* Or0 = O + gr0 * DD + h * 64;
    __half* Or1 = Or0 + (size_t)8 * DD;
    #pragma unroll
    for (int ni = 0; ni < 8; ni++) {
        const int cc = ni * 8 + 2 * t4;
        *(uint32_t*)(Or0 + cc) = packh2(co[ni][0] * inv0, co[ni][1] * inv0);
        *(uint32_t*)(Or1 + cc) = packh2(co[ni][2] * inv1, co[ni][3] * inv1);
    }
}

// ---------------- fused residual-add + LayerNorm ------------------------------
// WRITE_H: also writes fp16 copy (next GEMM's A operand).
template <bool WRITE_H>
__global__ __launch_bounds__(256) void add_ln_kernel(
    const float* __restrict__ A, const float* __restrict__ Bv,
    const float* __restrict__ g, const float* __restrict__ be,
    float* __restrict__ out, __half* __restrict__ out_h)
{
    const int row = blockIdx.x;
    const int tid = threadIdx.x;
    const size_t base = (size_t)row * DD + tid * 4;

    float4 av = *(const float4*)(A + base);
    float4 bv = *(const float4*)(Bv + base);
    float y0 = av.x + bv.x, y1 = av.y + bv.y, y2 = av.z + bv.z, y3 = av.w + bv.w;

    float s  = y0 + y1 + y2 + y3;
    float ss = y0 * y0 + y1 * y1 + y2 * y2 + y3 * y3;

    #pragma unroll
    for (int o = 16; o > 0; o >>= 1) {
        s  += __shfl_xor_sync(0xffffffffu, s, o);
        ss += __shfl_xor_sync(0xffffffffu, ss, o);
    }
    __shared__ float red_s[8], red_ss[8];
    const int wid = tid >> 5;
    if ((tid & 31) == 0) { red_s[wid] = s; red_ss[wid] = ss; }
    __syncthreads();
    float ts = 0.0f, tss = 0.0f;
    #pragma unroll
    for (int w = 0; w < 8; w++) { ts += red_s[w]; tss += red_ss[w]; }

    const float mu   = ts * (1.0f / DD);
    const float var  = tss * (1.0f / DD) - mu * mu;
    const float rstd = rsqrtf(var + 1e-5f);

    float4 gv  = *(const float4*)(g  + tid * 4);
    float4 bev = *(const float4*)(be + tid * 4);
    float4 ov;
    ov.x = (y0 - mu) * rstd * gv.x + bev.x;
    ov.y = (y1 - mu) * rstd * gv.y + bev.y;
    ov.z = (y2 - mu) * rstd * gv.z + bev.z;
    ov.w = (y3 - mu) * rstd * gv.w + bev.w;
    *(float4*)(out + base) = ov;
    if (WRITE_H) {
        uint2 o;
        o.x = packh2(ov.x, ov.y);
        o.y = packh2(ov.z, ov.w);
        *(uint2*)(out_h + base) = o;
    }
}

// ---------------- launch ------------------------------------------------------
extern "C" void kernel_launch(void* const* d_in, const int* in_sizes, int n_in,
                              void* d_out, int out_size)
{
    const float* x   = (const float*)d_in[0];
    const float* WQ  = (const float*)d_in[1];
    const float* bQ  = (const float*)d_in[2];
    const float* WK  = (const float*)d_in[3];
    const float* bK  = (const float*)d_in[4];
    const float* WV  = (const float*)d_in[5];
    const float* bV  = (const float*)d_in[6];
    const float* WO  = (const float*)d_in[7];
    const float* bO  = (const float*)d_in[8];
    const float* W1  = (const float*)d_in[9];
    const float* b1  = (const float*)d_in[10];
    const float* W2  = (const float*)d_in[11];
    const float* b2  = (const float*)d_in[12];
    const float* g1  = (const float*)d_in[13];
    const float* be1 = (const float*)d_in[14];
    const float* g2  = (const float*)d_in[15];
    const float* be2 = (const float*)d_in[16];
    float* out = (float*)d_out;

    __half *p_xh, *p_qkvh, *p_attnh, *p_x1h, *p_ffn1h;
    __half *p_wqkvh, *p_woh, *p_w1h, *p_w2h;
    float *p_proj, *p_x1, *p_ffn2, *p_bqkv;
    cudaGetSymbolAddress((void**)&p_xh,    g_xh);
    cudaGetSymbolAddress((void**)&p_qkvh,  g_qkvh);
    cudaGetSymbolAddress((void**)&p_attnh, g_attnh);
    cudaGetSymbolAddress((void**)&p_proj,  g_proj);
    cudaGetSymbolAddress((void**)&p_x1,    g_x1);
    cudaGetSymbolAddress((void**)&p_x1h,   g_x1h);
    cudaGetSymbolAddress((void**)&p_ffn1h, g_ffn1h);
    cudaGetSymbolAddress((void**)&p_ffn2,  g_ffn2);
    cudaGetSymbolAddress((void**)&p_wqkvh, g_wqkvh);
    cudaGetSymbolAddress((void**)&p_bqkv,  g_bqkv);
    cudaGetSymbolAddress((void**)&p_woh,   g_woh);
    cudaGetSymbolAddress((void**)&p_w1h,   g_w1h);
    cudaGetSymbolAddress((void**)&p_w2h,   g_w2h);

    cudaFuncSetAttribute(gemm_h<false, true>,
                         cudaFuncAttributeMaxDynamicSharedMemorySize, GEMM_SMEM);
    cudaFuncSetAttribute(gemm_h<false, false>,
                         cudaFuncAttributeMaxDynamicSharedMemorySize, GEMM_SMEM);
    cudaFuncSetAttribute(gemm_h<true, true>,
                         cudaFuncAttributeMaxDynamicSharedMemorySize, GEMM_SMEM);
    cudaFuncSetAttribute(attn_h_kernel,
                         cudaFuncAttributeMaxDynamicSharedMemorySize, ATTN_SMEM);

    // launch #0: ALL conversions + bias concat in one kernel
    cvt_all_kernel<<<2048, 256>>>(WQ, WK, WV, WO, W1, W2, x, bQ, bK, bV);

    const dim3 gQKV(QKVS / 128, MM / 128);   // (24, 64)
    const dim3 gD(DD / 128, MM / 128);       // (8, 64)
    const dim3 gF(FFN / 128, MM / 128);      // (32, 64)

    // #1: fused QKV projection (fp16 out)
    gemm_h<false, true><<<gQKV, 256, GEMM_SMEM>>>(p_xh, p_wqkvh, p_bqkv,
                                                  nullptr, p_qkvh, MM, QKVS, DD);

    // #2: causal attention (fp16)
    attn_h_kernel<<<dim3(TT / 64, HH, BB), 128, ATTN_SMEM>>>(p_qkvh, p_attnh);

    // #3: output projection (fp32 out); #4: LN1 (fp32 residual + fp16 copy)
    gemm_h<false, false><<<gD, 256, GEMM_SMEM>>>(p_attnh, p_woh, bO,
                                                 p_proj, nullptr, MM, DD, DD);
    add_ln_kernel<true><<<MM, 256>>>(x, p_proj, g1, be1, p_x1, p_x1h);

    // #5: W1 FFN GEMM (the launch ncu -s 5 will profile); #6: W2; #7: LN2
    gemm_h<true, true><<<gF, 256, GEMM_SMEM>>>(p_x1h, p_w1h, b1,
                                               nullptr, p_ffn1h, MM, FFN, DD);
    gemm_h<false, false><<<gD, 256, GEMM_SMEM>>>(p_ffn1h, p_w2h, b2,
                                                 p_ffn2, nullptr, MM, DD, FFN);
    add_ln_kernel<false><<<MM, 256>>>(p_x1, p_ffn2, g2, be2, out, nullptr);
}